// round 2
// baseline (speedup 1.0000x reference)
#include <cuda_runtime.h>
#include <math.h>

// Problem constants
#define B_   2
#define S_   2048
#define D_   1024
#define H_   16
#define HD_  64
#define M_TOT (B_*S_)     // 4096 rows (B*S)
#define N_QKV (3*D_)      // 3072

// Scratch (allocation-free rule: __device__ globals)
__device__ float g_qkv [(size_t)M_TOT * N_QKV];  // [B*S, 3*D] : per-head q/k/v at h*192 + {0,64,128}
__device__ float g_attn[(size_t)M_TOT * D_];     // [B*S, D] attention output (pre out-proj)

// ---------------------------------------------------------------------------
// NT SGEMM: C[M,N] = A[M,K] @ B[N,K]^T (+ bias[n])
// MODE 0: A = param, C = g_qkv        (QKV projection)
// MODE 1: A = g_attn, C = param+bias  (output projection)
// Requires M%128==0, N%128==0, K%16==0 (true for all our shapes).
// ---------------------------------------------------------------------------
template<int MODE>
__global__ __launch_bounds__(256, 2)
void sgemm_nt(const float* __restrict__ A_in, const float* __restrict__ Bm,
              const float* __restrict__ bias, float* __restrict__ C_in,
              int M, int N, int K)
{
    constexpr int BM = 128, BN = 128, BK = 16;
    constexpr int LDA = BM + 4;   // pad keeps float4 alignment (stride 528B % 16 == 0)
    __shared__ float As[BK][LDA];
    __shared__ float Bs[BK][LDA];

    const float* A = (MODE == 1) ? (const float*)g_attn : A_in;
    float*       C = (MODE == 0) ? (float*)g_qkv       : C_in;

    const int tid  = threadIdx.x;
    const int warp = tid >> 5, lane = tid & 31;
    const int wr = warp >> 1, wc = warp & 1;   // 4x2 warp grid
    const int lr = lane >> 3, lc = lane & 7;   // 4x8 lane grid
    const int row0 = wr * 32 + lr * 8;
    const int col0 = wc * 64 + lc * 8;

    const int bm = blockIdx.y * BM;
    const int bn = blockIdx.x * BN;

    const float* Ap = A  + (size_t)bm * K;
    const float* Bp = Bm + (size_t)bn * K;

    float acc[8][8] = {};

    for (int k0 = 0; k0 < K; k0 += BK) {
        // 512 float4 per operand tile; 2 per thread
        #pragma unroll
        for (int i = 0; i < 2; i++) {
            int f4 = tid + i * 256;
            int r  = f4 >> 2;
            int c4 = (f4 & 3) << 2;
            float4 av = *(const float4*)(Ap + (size_t)r * K + k0 + c4);
            float4 bv = *(const float4*)(Bp + (size_t)r * K + k0 + c4);
            As[c4+0][r] = av.x; As[c4+1][r] = av.y; As[c4+2][r] = av.z; As[c4+3][r] = av.w;
            Bs[c4+0][r] = bv.x; Bs[c4+1][r] = bv.y; Bs[c4+2][r] = bv.z; Bs[c4+3][r] = bv.w;
        }
        __syncthreads();

        #pragma unroll
        for (int k = 0; k < BK; k++) {
            float ar[8], br[8];
            *(float4*)&ar[0] = *(const float4*)&As[k][row0];
            *(float4*)&ar[4] = *(const float4*)&As[k][row0 + 4];
            *(float4*)&br[0] = *(const float4*)&Bs[k][col0];
            *(float4*)&br[4] = *(const float4*)&Bs[k][col0 + 4];
            #pragma unroll
            for (int i = 0; i < 8; i++)
                #pragma unroll
                for (int j = 0; j < 8; j++)
                    acc[i][j] += ar[i] * br[j];
        }
        __syncthreads();
    }

    #pragma unroll
    for (int i = 0; i < 8; i++) {
        int r = bm + row0 + i;
        #pragma unroll
        for (int j = 0; j < 8; j += 4) {
            int c = bn + col0 + j;
            float4 v = make_float4(acc[i][j], acc[i][j+1], acc[i][j+2], acc[i][j+3]);
            if (MODE == 1) {
                v.x += bias[c]; v.y += bias[c+1]; v.z += bias[c+2]; v.w += bias[c+3];
            }
            *(float4*)(C + (size_t)r * N + c) = v;
        }
    }
}

// ---------------------------------------------------------------------------
// Fused causal flash-attention, fp32.
// One q-row per thread (128 q rows / block), K/V tiles of 64 keys in smem,
// online softmax in 16-key chunks (keeps s[] fully register-resident).
// scores = (q . k) * (1/HD)  [note: reference divides by d_k, not sqrt(d_k)]
// ---------------------------------------------------------------------------
__global__ __launch_bounds__(128)
void attn_kernel()
{
    __shared__ float Ks[64 * 64];
    __shared__ float Vs[64 * 64];

    const int tid = threadIdx.x;
    const int bh  = blockIdx.y;            // b*H + h
    const int b   = bh >> 4;
    const int h   = bh & 15;
    const int qg  = blockIdx.x * 128 + tid;   // global query index in [0, S)

    // Per-head base offsets inside g_qkv [B*S, 3072]
    const size_t head_off = (size_t)h * (3 * HD_);
    const size_t seq_base = (size_t)(b * S_) * N_QKV;

    // Load this thread's q row
    float q[64];
    {
        const float* qrow = g_qkv + seq_base + (size_t)qg * N_QKV + head_off;
        #pragma unroll
        for (int i = 0; i < 16; i++)
            *(float4*)&q[i * 4] = *(const float4*)(qrow + i * 4);
    }

    float o[64];
    #pragma unroll
    for (int i = 0; i < 64; i++) o[i] = 0.f;
    float mrow = -INFINITY, lrow = 0.f;

    const int ntiles = (blockIdx.x + 1) * 2;          // keys up to bx*128+127
    const size_t kbase = seq_base + head_off + HD_;   // K columns
    const size_t vbase = kbase + HD_;                  // V columns

    for (int t = 0; t < ntiles; t++) {
        // Cooperative K/V tile load: 64 rows x 64 floats each
        #pragma unroll
        for (int i = 0; i < 8; i++) {
            int f4 = i * 128 + tid;
            int r  = f4 >> 4;
            int c  = (f4 & 15) << 2;
            size_t roff = (size_t)(t * 64 + r) * N_QKV;
            *(float4*)&Ks[r * 64 + c] = *(const float4*)(g_qkv + kbase + roff + c);
            *(float4*)&Vs[r * 64 + c] = *(const float4*)(g_qkv + vbase + roff + c);
        }
        __syncthreads();

        #pragma unroll 1
        for (int cc = 0; cc < 4; cc++) {          // 16-key softmax chunks
            float s[16];
            #pragma unroll
            for (int j = 0; j < 16; j++) {
                const float* kr = Ks + (cc * 16 + j) * 64;
                float d0 = 0.f, d1 = 0.f, d2 = 0.f, d3 = 0.f;
                #pragma unroll
                for (int d4 = 0; d4 < 16; d4++) {
                    float4 kv = *(const float4*)(kr + d4 * 4);
                    d0 += q[d4 * 4 + 0] * kv.x;
                    d1 += q[d4 * 4 + 1] * kv.y;
                    d2 += q[d4 * 4 + 2] * kv.z;
                    d3 += q[d4 * 4 + 3] * kv.w;
                }
                int kk = t * 64 + cc * 16 + j;
                float dot = (d0 + d1) + (d2 + d3);
                s[j] = (kk <= qg) ? dot * (1.0f / HD_) : -INFINITY;
            }
            float cmax = s[0];
            #pragma unroll
            for (int j = 1; j < 16; j++) cmax = fmaxf(cmax, s[j]);
            float mnew  = fmaxf(mrow, cmax);
            float scale = __expf(mrow - mnew);    // 0 when mrow == -inf (first chunk)
            float lsum  = 0.f;
            #pragma unroll
            for (int j = 0; j < 16; j++) { s[j] = __expf(s[j] - mnew); lsum += s[j]; }
            lrow = lrow * scale + lsum;
            mrow = mnew;
            #pragma unroll
            for (int i = 0; i < 64; i++) o[i] *= scale;
            #pragma unroll
            for (int j = 0; j < 16; j++) {
                const float* vr = Vs + (cc * 16 + j) * 64;
                float pj = s[j];
                #pragma unroll
                for (int d4 = 0; d4 < 16; d4++) {
                    float4 vv = *(const float4*)(vr + d4 * 4);
                    o[d4 * 4 + 0] += pj * vv.x;
                    o[d4 * 4 + 1] += pj * vv.y;
                    o[d4 * 4 + 2] += pj * vv.z;
                    o[d4 * 4 + 3] += pj * vv.w;
                }
            }
        }
        __syncthreads();
    }

    const float inv_l = 1.0f / lrow;
    float* orow = g_attn + (size_t)(b * S_ + qg) * D_ + (size_t)h * HD_;
    #pragma unroll
    for (int i = 0; i < 16; i++) {
        float4 v = make_float4(o[i*4+0] * inv_l, o[i*4+1] * inv_l,
                               o[i*4+2] * inv_l, o[i*4+3] * inv_l);
        *(float4*)(orow + i * 4) = v;
    }
}

// ---------------------------------------------------------------------------
extern "C" void kernel_launch(void* const* d_in, const int* in_sizes, int n_in,
                              void* d_out, int out_size)
{
    // Identify inputs by element count (robust to metadata ordering)
    const float* x = nullptr, *w_qkv = nullptr, *w_out = nullptr, *b_out = nullptr;
    for (int i = 0; i < n_in; i++) {
        long long n = in_sizes[i];
        if      (n == (long long)B_ * S_ * D_)      x     = (const float*)d_in[i];
        else if (n == (long long)N_QKV * D_)        w_qkv = (const float*)d_in[i];
        else if (n == (long long)D_ * D_)           w_out = (const float*)d_in[i];
        else if (n == (long long)D_)                b_out = (const float*)d_in[i];
        // mask (B*S*S elements) is ignored: causality is static
    }
    float* out = (float*)d_out;

    // 1) QKV projection: g_qkv[B*S, 3072] = x @ w_qkv^T
    sgemm_nt<0><<<dim3(N_QKV / 128, M_TOT / 128), 256>>>(
        x, w_qkv, nullptr, nullptr, M_TOT, N_QKV, D_);

    // 2) Fused causal attention -> g_attn[B*S, 1024]
    attn_kernel<<<dim3(S_ / 128, B_ * H_), 128>>>();

    // 3) Output projection: out = g_attn @ w_out^T + b_out
    sgemm_nt<1><<<dim3(D_ / 128, M_TOT / 128), 256>>>(
        nullptr, w_out, b_out, out, M_TOT, D_, D_);
}

// round 4
// speedup vs baseline: 1.2986x; 1.2986x over previous
#include <cuda_runtime.h>
#include <cuda_bf16.h>
#include <stdint.h>
#include <math.h>

// Problem constants
#define B_   2
#define S_   2048
#define D_   1024
#define H_   16
#define HD_  64
#define M_TOT (B_*S_)     // 4096
#define N_QKV (3*D_)      // 3072

// ---------------------------------------------------------------------------
// Scratch (allocation-free rule: __device__ globals)
// ---------------------------------------------------------------------------
__device__ float g_qkv [(size_t)M_TOT * N_QKV];  // [B*S, 3*D]
__device__ float g_attn[(size_t)M_TOT * D_];     // [B*S, D]

// bf16 hi/lo split operands for tensor-core GEMMs
__device__ __nv_bfloat16 g_x_hi [(size_t)M_TOT * D_];
__device__ __nv_bfloat16 g_x_lo [(size_t)M_TOT * D_];
__device__ __nv_bfloat16 g_wq_hi[(size_t)N_QKV * D_];
__device__ __nv_bfloat16 g_wq_lo[(size_t)N_QKV * D_];
__device__ __nv_bfloat16 g_at_hi[(size_t)M_TOT * D_];
__device__ __nv_bfloat16 g_at_lo[(size_t)M_TOT * D_];
__device__ __nv_bfloat16 g_wo_hi[(size_t)D_ * D_];
__device__ __nv_bfloat16 g_wo_lo[(size_t)D_ * D_];

// ---------------------------------------------------------------------------
// Elementwise split: a -> (hi, lo) bf16 with hi = rn(a), lo = rn(a - hi)
// ID selects destination arrays (and source for ID==2).
// ---------------------------------------------------------------------------
template<int ID>
__global__ void split_bf16(const float* __restrict__ src_in, int n4)
{
    const float* src = (ID == 2) ? (const float*)g_attn : src_in;
    __nv_bfloat16* hi = (ID == 0) ? g_x_hi : (ID == 1) ? g_wq_hi
                       : (ID == 2) ? g_at_hi : g_wo_hi;
    __nv_bfloat16* lo = (ID == 0) ? g_x_lo : (ID == 1) ? g_wq_lo
                       : (ID == 2) ? g_at_lo : g_wo_lo;

    for (int i = blockIdx.x * blockDim.x + threadIdx.x; i < n4;
         i += gridDim.x * blockDim.x) {
        float4 v = ((const float4*)src)[i];
        __nv_bfloat16 h0 = __float2bfloat16_rn(v.x);
        __nv_bfloat16 h1 = __float2bfloat16_rn(v.y);
        __nv_bfloat16 h2 = __float2bfloat16_rn(v.z);
        __nv_bfloat16 h3 = __float2bfloat16_rn(v.w);
        __nv_bfloat16 l0 = __float2bfloat16_rn(v.x - __bfloat162float(h0));
        __nv_bfloat16 l1 = __float2bfloat16_rn(v.y - __bfloat162float(h1));
        __nv_bfloat16 l2 = __float2bfloat16_rn(v.z - __bfloat162float(h2));
        __nv_bfloat16 l3 = __float2bfloat16_rn(v.w - __bfloat162float(h3));
        ((__nv_bfloat162*)hi)[2*i + 0] = __nv_bfloat162(h0, h1);
        ((__nv_bfloat162*)hi)[2*i + 1] = __nv_bfloat162(h2, h3);
        ((__nv_bfloat162*)lo)[2*i + 0] = __nv_bfloat162(l0, l1);
        ((__nv_bfloat162*)lo)[2*i + 1] = __nv_bfloat162(l2, l3);
    }
}

// ---------------------------------------------------------------------------
// bf16x3-split tensor-core NT GEMM: C[M,N] = A[M,K] @ B[N,K]^T (+ bias)
//   a*b ~= a_hi*b_hi + a_hi*b_lo + a_lo*b_hi  (fp32 accumulate)
// MODE 0: A = x splits,    B = w_qkv splits, C = g_qkv
// MODE 1: A = attn splits, B = w_out splits, C = d_out + bias
// Tile: BM=128, BN=128, BK=16. 8 warps, each 32x64. cp.async double buffer.
// ---------------------------------------------------------------------------
__device__ __forceinline__ void mma16816(float* c, const uint32_t* a, const uint32_t* b)
{
    asm volatile(
        "mma.sync.aligned.m16n8k16.row.col.f32.bf16.bf16.f32 "
        "{%0,%1,%2,%3}, {%4,%5,%6,%7}, {%8,%9}, {%0,%1,%2,%3};\n"
        : "+f"(c[0]), "+f"(c[1]), "+f"(c[2]), "+f"(c[3])
        : "r"(a[0]), "r"(a[1]), "r"(a[2]), "r"(a[3]), "r"(b[0]), "r"(b[1]));
}

template<int MODE>
__global__ __launch_bounds__(256)
void gemm_bf16x3(const float* __restrict__ bias, float* __restrict__ C_out,
                 int M, int N, int K)
{
    constexpr int BK  = 16;
    constexpr int LDW = 12;   // uint32 words per row: 8 used + 4 pad (conflict-free)
    // [buf][arr][row*LDW + word] ; arr: 0=A_hi 1=A_lo 2=B_hi 3=B_lo  (48KB exactly)
    __shared__ uint32_t sm[2][4][128 * LDW];

    const __nv_bfloat16 *Ah, *Al, *Bh, *Bl;
    float* C;
    if (MODE == 0) { Ah = g_x_hi;  Al = g_x_lo;  Bh = g_wq_hi; Bl = g_wq_lo; C = g_qkv; }
    else           { Ah = g_at_hi; Al = g_at_lo; Bh = g_wo_hi; Bl = g_wo_lo; C = C_out; }

    const int tid  = threadIdx.x;
    const int lane = tid & 31;
    const int warp = tid >> 5;
    const int wr = warp >> 1, wc = warp & 1;     // 4x2 warp grid (rows x cols)
    const int gid = lane >> 2, tig = lane & 3;

    const int bm = blockIdx.y * 128;
    const int bn = blockIdx.x * 128;

    // cp.async loader mapping: each thread moves one 16B chunk per split array.
    const int lrow  = tid >> 1;          // 0..127
    const int lhalf = (tid & 1) * 8;     // bf16 column offset 0 or 8
    const size_t a_src0 = (size_t)(bm + lrow) * K + lhalf;
    const size_t b_src0 = (size_t)(bn + lrow) * K + lhalf;
    const uint32_t dst_byte = (uint32_t)(lrow * LDW + (tid & 1) * 4) * 4;

    uint32_t sbase[2][4];
    #pragma unroll
    for (int bf = 0; bf < 2; bf++)
        #pragma unroll
        for (int ar = 0; ar < 4; ar++)
            sbase[bf][ar] = (uint32_t)__cvta_generic_to_shared(&sm[bf][ar][0]);

    #define LOAD_TILE(T, BUF) do {                                             \
        int k0_ = (T) * BK;                                                    \
        asm volatile("cp.async.cg.shared.global [%0], [%1], 16;\n"             \
            :: "r"(sbase[BUF][0] + dst_byte), "l"(Ah + a_src0 + k0_));         \
        asm volatile("cp.async.cg.shared.global [%0], [%1], 16;\n"             \
            :: "r"(sbase[BUF][1] + dst_byte), "l"(Al + a_src0 + k0_));         \
        asm volatile("cp.async.cg.shared.global [%0], [%1], 16;\n"             \
            :: "r"(sbase[BUF][2] + dst_byte), "l"(Bh + b_src0 + k0_));         \
        asm volatile("cp.async.cg.shared.global [%0], [%1], 16;\n"             \
            :: "r"(sbase[BUF][3] + dst_byte), "l"(Bl + b_src0 + k0_));         \
    } while (0)

    float acc[2][8][4] = {};

    const int nt = K / BK;
    LOAD_TILE(0, 0);
    asm volatile("cp.async.commit_group;\n");

    for (int t = 0; t < nt; t++) {
        const int buf = t & 1;
        if (t + 1 < nt) {
            LOAD_TILE(t + 1, (t + 1) & 1);
            asm volatile("cp.async.commit_group;\n");
            asm volatile("cp.async.wait_group 1;\n");
        } else {
            asm volatile("cp.async.wait_group 0;\n");
        }
        __syncthreads();

        const uint32_t* pAh = &sm[buf][0][0];
        const uint32_t* pAl = &sm[buf][1][0];
        const uint32_t* pBh = &sm[buf][2][0];
        const uint32_t* pBl = &sm[buf][3][0];

        uint32_t ah[2][4], al[2][4];
        #pragma unroll
        for (int mi = 0; mi < 2; mi++) {
            int r0 = wr * 32 + mi * 16 + gid;
            ah[mi][0] = pAh[ r0      * LDW + tig    ];
            ah[mi][1] = pAh[(r0 + 8) * LDW + tig    ];
            ah[mi][2] = pAh[ r0      * LDW + tig + 4];
            ah[mi][3] = pAh[(r0 + 8) * LDW + tig + 4];
            al[mi][0] = pAl[ r0      * LDW + tig    ];
            al[mi][1] = pAl[(r0 + 8) * LDW + tig    ];
            al[mi][2] = pAl[ r0      * LDW + tig + 4];
            al[mi][3] = pAl[(r0 + 8) * LDW + tig + 4];
        }
        #pragma unroll
        for (int ni = 0; ni < 8; ni++) {
            int nr = wc * 64 + ni * 8 + gid;
            uint32_t bh[2], bl[2];
            bh[0] = pBh[nr * LDW + tig];
            bh[1] = pBh[nr * LDW + tig + 4];
            bl[0] = pBl[nr * LDW + tig];
            bl[1] = pBl[nr * LDW + tig + 4];
            #pragma unroll
            for (int mi = 0; mi < 2; mi++) {
                mma16816(acc[mi][ni], ah[mi], bh);
                mma16816(acc[mi][ni], ah[mi], bl);
                mma16816(acc[mi][ni], al[mi], bh);
            }
        }
        __syncthreads();
    }
    #undef LOAD_TILE

    // Epilogue
    #pragma unroll
    for (int mi = 0; mi < 2; mi++) {
        int row = bm + wr * 32 + mi * 16 + gid;
        #pragma unroll
        for (int ni = 0; ni < 8; ni++) {
            int col = bn + wc * 64 + ni * 8 + tig * 2;
            float2 v0 = make_float2(acc[mi][ni][0], acc[mi][ni][1]);
            float2 v1 = make_float2(acc[mi][ni][2], acc[mi][ni][3]);
            if (MODE == 1) {
                float2 bv = *(const float2*)(bias + col);
                v0.x += bv.x; v0.y += bv.y;
                v1.x += bv.x; v1.y += bv.y;
            }
            *(float2*)(C + (size_t)row * N + col)       = v0;
            *(float2*)(C + (size_t)(row + 8) * N + col) = v1;
        }
    }
}

// ---------------------------------------------------------------------------
// Fused causal flash-attention, fp32 (unchanged from R1).
// ---------------------------------------------------------------------------
__global__ __launch_bounds__(128)
void attn_kernel()
{
    __shared__ float Ks[64 * 64];
    __shared__ float Vs[64 * 64];

    const int tid = threadIdx.x;
    const int bh  = blockIdx.y;
    const int b   = bh >> 4;
    const int h   = bh & 15;
    const int qg  = blockIdx.x * 128 + tid;

    const size_t head_off = (size_t)h * (3 * HD_);
    const size_t seq_base = (size_t)(b * S_) * N_QKV;

    float q[64];
    {
        const float* qrow = g_qkv + seq_base + (size_t)qg * N_QKV + head_off;
        #pragma unroll
        for (int i = 0; i < 16; i++)
            *(float4*)&q[i * 4] = *(const float4*)(qrow + i * 4);
    }

    float o[64];
    #pragma unroll
    for (int i = 0; i < 64; i++) o[i] = 0.f;
    float mrow = -INFINITY, lrow = 0.f;

    const int ntiles = (blockIdx.x + 1) * 2;
    const size_t kbase = seq_base + head_off + HD_;
    const size_t vbase = kbase + HD_;

    for (int t = 0; t < ntiles; t++) {
        #pragma unroll
        for (int i = 0; i < 8; i++) {
            int f4 = i * 128 + tid;
            int r  = f4 >> 4;
            int c  = (f4 & 15) << 2;
            size_t roff = (size_t)(t * 64 + r) * N_QKV;
            *(float4*)&Ks[r * 64 + c] = *(const float4*)(g_qkv + kbase + roff + c);
            *(float4*)&Vs[r * 64 + c] = *(const float4*)(g_qkv + vbase + roff + c);
        }
        __syncthreads();

        #pragma unroll 1
        for (int cc = 0; cc < 4; cc++) {
            float s[16];
            #pragma unroll
            for (int j = 0; j < 16; j++) {
                const float* kr = Ks + (cc * 16 + j) * 64;
                float d0 = 0.f, d1 = 0.f, d2 = 0.f, d3 = 0.f;
                #pragma unroll
                for (int d4 = 0; d4 < 16; d4++) {
                    float4 kv = *(const float4*)(kr + d4 * 4);
                    d0 += q[d4 * 4 + 0] * kv.x;
                    d1 += q[d4 * 4 + 1] * kv.y;
                    d2 += q[d4 * 4 + 2] * kv.z;
                    d3 += q[d4 * 4 + 3] * kv.w;
                }
                int kk = t * 64 + cc * 16 + j;
                float dot = (d0 + d1) + (d2 + d3);
                s[j] = (kk <= qg) ? dot * (1.0f / HD_) : -INFINITY;
            }
            float cmax = s[0];
            #pragma unroll
            for (int j = 1; j < 16; j++) cmax = fmaxf(cmax, s[j]);
            float mnew  = fmaxf(mrow, cmax);
            float scale = __expf(mrow - mnew);
            float lsum  = 0.f;
            #pragma unroll
            for (int j = 0; j < 16; j++) { s[j] = __expf(s[j] - mnew); lsum += s[j]; }
            lrow = lrow * scale + lsum;
            mrow = mnew;
            #pragma unroll
            for (int i = 0; i < 64; i++) o[i] *= scale;
            #pragma unroll
            for (int j = 0; j < 16; j++) {
                const float* vr = Vs + (cc * 16 + j) * 64;
                float pj = s[j];
                #pragma unroll
                for (int d4 = 0; d4 < 16; d4++) {
                    float4 vv = *(const float4*)(vr + d4 * 4);
                    o[d4 * 4 + 0] += pj * vv.x;
                    o[d4 * 4 + 1] += pj * vv.y;
                    o[d4 * 4 + 2] += pj * vv.z;
                    o[d4 * 4 + 3] += pj * vv.w;
                }
            }
        }
        __syncthreads();
    }

    const float inv_l = 1.0f / lrow;
    float* orow = g_attn + (size_t)(b * S_ + qg) * D_ + (size_t)h * HD_;
    #pragma unroll
    for (int i = 0; i < 16; i++) {
        float4 v = make_float4(o[i*4+0] * inv_l, o[i*4+1] * inv_l,
                               o[i*4+2] * inv_l, o[i*4+3] * inv_l);
        *(float4*)(orow + i * 4) = v;
    }
}

// ---------------------------------------------------------------------------
extern "C" void kernel_launch(void* const* d_in, const int* in_sizes, int n_in,
                              void* d_out, int out_size)
{
    const float* x = nullptr, *w_qkv = nullptr, *w_out = nullptr, *b_out = nullptr;
    for (int i = 0; i < n_in; i++) {
        long long n = in_sizes[i];
        if      (n == (long long)B_ * S_ * D_)      x     = (const float*)d_in[i];
        else if (n == (long long)N_QKV * D_)        w_qkv = (const float*)d_in[i];
        else if (n == (long long)D_ * D_)           w_out = (const float*)d_in[i];
        else if (n == (long long)D_)                b_out = (const float*)d_in[i];
        // mask ignored: causality is static
    }
    float* out = (float*)d_out;

    // 0) Split inputs/weights into bf16 hi/lo
    split_bf16<0><<<4096, 256>>>(x,     (M_TOT * D_) / 4);
    split_bf16<1><<<3072, 256>>>(w_qkv, (N_QKV * D_) / 4);
    split_bf16<3><<<1024, 256>>>(w_out, (D_ * D_) / 4);

    // 1) QKV projection (tensor cores): g_qkv = x @ w_qkv^T
    gemm_bf16x3<0><<<dim3(N_QKV / 128, M_TOT / 128), 256>>>(
        nullptr, nullptr, M_TOT, N_QKV, D_);

    // 2) Fused causal attention -> g_attn
    attn_kernel<<<dim3(S_ / 128, B_ * H_), 128>>>();

    // 3) Split attention output, then out-projection (tensor cores)
    split_bf16<2><<<4096, 256>>>(nullptr, (M_TOT * D_) / 4);
    gemm_bf16x3<1><<<dim3(D_ / 128, M_TOT / 128), 256>>>(
        b_out, out, M_TOT, D_, D_);
}

// round 6
// speedup vs baseline: 2.5363x; 1.9531x over previous
#include <cuda_runtime.h>
#include <cuda_bf16.h>
#include <stdint.h>
#include <math.h>

// Problem constants
#define B_   2
#define S_   2048
#define D_   1024
#define H_   16
#define HD_  64
#define M_TOT (B_*S_)     // 4096
#define N_QKV (3*D_)      // 3072

// ---------------------------------------------------------------------------
// Scratch (allocation-free rule: __device__ globals)
// ---------------------------------------------------------------------------
__device__ float g_qkv [(size_t)M_TOT * N_QKV];  // [B*S, 3*D]

// bf16 hi/lo split operands for the projection GEMMs
__device__ __nv_bfloat16 g_x_hi [(size_t)M_TOT * D_];
__device__ __nv_bfloat16 g_x_lo [(size_t)M_TOT * D_];
__device__ __nv_bfloat16 g_wq_hi[(size_t)N_QKV * D_];
__device__ __nv_bfloat16 g_wq_lo[(size_t)N_QKV * D_];
__device__ __nv_bfloat16 g_at_hi[(size_t)M_TOT * D_];   // attention out (split)
__device__ __nv_bfloat16 g_at_lo[(size_t)M_TOT * D_];
__device__ __nv_bfloat16 g_wo_hi[(size_t)D_ * D_];
__device__ __nv_bfloat16 g_wo_lo[(size_t)D_ * D_];

// Head-contiguous attention operands (split), from repack kernel
__device__ __nv_bfloat16 g_aq_hi [(size_t)B_*H_*S_*HD_];  // [bh][S][64], q/64
__device__ __nv_bfloat16 g_aq_lo [(size_t)B_*H_*S_*HD_];
__device__ __nv_bfloat16 g_ak_hi [(size_t)B_*H_*S_*HD_];  // [bh][S][64]
__device__ __nv_bfloat16 g_ak_lo [(size_t)B_*H_*S_*HD_];
__device__ __nv_bfloat16 g_avt_hi[(size_t)B_*H_*HD_*S_];  // [bh][64][S]  (V^T)
__device__ __nv_bfloat16 g_avt_lo[(size_t)B_*H_*HD_*S_];

// ---------------------------------------------------------------------------
// helpers
// ---------------------------------------------------------------------------
__device__ __forceinline__ uint32_t pack_bf2(float lo, float hi) {
    __nv_bfloat162 t = __floats2bfloat162_rn(lo, hi);   // .x = lo half
    return *(uint32_t*)&t;
}
__device__ __forceinline__ void split1(float v, float& h, float& l) {
    __nv_bfloat16 hb = __float2bfloat16_rn(v);
    h = __bfloat162float(hb);
    l = v - h;
}

__device__ __forceinline__ void mma16816(float* c, const uint32_t* a, const uint32_t* b)
{
    asm volatile(
        "mma.sync.aligned.m16n8k16.row.col.f32.bf16.bf16.f32 "
        "{%0,%1,%2,%3}, {%4,%5,%6,%7}, {%8,%9}, {%0,%1,%2,%3};\n"
        : "+f"(c[0]), "+f"(c[1]), "+f"(c[2]), "+f"(c[3])
        : "r"(a[0]), "r"(a[1]), "r"(a[2]), "r"(a[3]), "r"(b[0]), "r"(b[1]));
}

// ---------------------------------------------------------------------------
// Elementwise split for GEMM inputs: a -> (hi, lo)
// ---------------------------------------------------------------------------
template<int ID>
__global__ void split_bf16(const float* __restrict__ src, int n4)
{
    __nv_bfloat16* hi = (ID == 0) ? g_x_hi : (ID == 1) ? g_wq_hi : g_wo_hi;
    __nv_bfloat16* lo = (ID == 0) ? g_x_lo : (ID == 1) ? g_wq_lo : g_wo_lo;

    for (int i = blockIdx.x * blockDim.x + threadIdx.x; i < n4;
         i += gridDim.x * blockDim.x) {
        float4 v = ((const float4*)src)[i];
        float h0,l0,h1,l1,h2,l2,h3,l3;
        split1(v.x,h0,l0); split1(v.y,h1,l1); split1(v.z,h2,l2); split1(v.w,h3,l3);
        ((uint32_t*)hi)[2*i + 0] = pack_bf2(h0, h1);
        ((uint32_t*)hi)[2*i + 1] = pack_bf2(h2, h3);
        ((uint32_t*)lo)[2*i + 0] = pack_bf2(l0, l1);
        ((uint32_t*)lo)[2*i + 1] = pack_bf2(l2, l3);
    }
}

// ---------------------------------------------------------------------------
// bf16x3-split tensor-core NT GEMM (unchanged from R4)
// ---------------------------------------------------------------------------
template<int MODE>
__global__ __launch_bounds__(256)
void gemm_bf16x3(const float* __restrict__ bias, float* __restrict__ C_out,
                 int M, int N, int K)
{
    constexpr int BK  = 16;
    constexpr int LDW = 12;
    __shared__ uint32_t sm[2][4][128 * LDW];

    const __nv_bfloat16 *Ah, *Al, *Bh, *Bl;
    float* C;
    if (MODE == 0) { Ah = g_x_hi;  Al = g_x_lo;  Bh = g_wq_hi; Bl = g_wq_lo; C = g_qkv; }
    else           { Ah = g_at_hi; Al = g_at_lo; Bh = g_wo_hi; Bl = g_wo_lo; C = C_out; }

    const int tid  = threadIdx.x;
    const int lane = tid & 31;
    const int warp = tid >> 5;
    const int wr = warp >> 1, wc = warp & 1;
    const int gid = lane >> 2, tig = lane & 3;

    const int bm = blockIdx.y * 128;
    const int bn = blockIdx.x * 128;

    const int lrow  = tid >> 1;
    const int lhalf = (tid & 1) * 8;
    const size_t a_src0 = (size_t)(bm + lrow) * K + lhalf;
    const size_t b_src0 = (size_t)(bn + lrow) * K + lhalf;
    const uint32_t dst_byte = (uint32_t)(lrow * LDW + (tid & 1) * 4) * 4;

    uint32_t sbase[2][4];
    #pragma unroll
    for (int bf = 0; bf < 2; bf++)
        #pragma unroll
        for (int ar = 0; ar < 4; ar++)
            sbase[bf][ar] = (uint32_t)__cvta_generic_to_shared(&sm[bf][ar][0]);

    #define LOAD_TILE(T, BUF) do {                                             \
        int k0_ = (T) * BK;                                                    \
        asm volatile("cp.async.cg.shared.global [%0], [%1], 16;\n"             \
            :: "r"(sbase[BUF][0] + dst_byte), "l"(Ah + a_src0 + k0_));         \
        asm volatile("cp.async.cg.shared.global [%0], [%1], 16;\n"             \
            :: "r"(sbase[BUF][1] + dst_byte), "l"(Al + a_src0 + k0_));         \
        asm volatile("cp.async.cg.shared.global [%0], [%1], 16;\n"             \
            :: "r"(sbase[BUF][2] + dst_byte), "l"(Bh + b_src0 + k0_));         \
        asm volatile("cp.async.cg.shared.global [%0], [%1], 16;\n"             \
            :: "r"(sbase[BUF][3] + dst_byte), "l"(Bl + b_src0 + k0_));         \
    } while (0)

    float acc[2][8][4] = {};

    const int nt = K / BK;
    LOAD_TILE(0, 0);
    asm volatile("cp.async.commit_group;\n");

    for (int t = 0; t < nt; t++) {
        const int buf = t & 1;
        if (t + 1 < nt) {
            LOAD_TILE(t + 1, (t + 1) & 1);
            asm volatile("cp.async.commit_group;\n");
            asm volatile("cp.async.wait_group 1;\n");
        } else {
            asm volatile("cp.async.wait_group 0;\n");
        }
        __syncthreads();

        const uint32_t* pAh = &sm[buf][0][0];
        const uint32_t* pAl = &sm[buf][1][0];
        const uint32_t* pBh = &sm[buf][2][0];
        const uint32_t* pBl = &sm[buf][3][0];

        uint32_t ah[2][4], al[2][4];
        #pragma unroll
        for (int mi = 0; mi < 2; mi++) {
            int r0 = wr * 32 + mi * 16 + gid;
            ah[mi][0] = pAh[ r0      * LDW + tig    ];
            ah[mi][1] = pAh[(r0 + 8) * LDW + tig    ];
            ah[mi][2] = pAh[ r0      * LDW + tig + 4];
            ah[mi][3] = pAh[(r0 + 8) * LDW + tig + 4];
            al[mi][0] = pAl[ r0      * LDW + tig    ];
            al[mi][1] = pAl[(r0 + 8) * LDW + tig    ];
            al[mi][2] = pAl[ r0      * LDW + tig + 4];
            al[mi][3] = pAl[(r0 + 8) * LDW + tig + 4];
        }
        #pragma unroll
        for (int ni = 0; ni < 8; ni++) {
            int nr = wc * 64 + ni * 8 + gid;
            uint32_t bh2[2], bl2[2];
            bh2[0] = pBh[nr * LDW + tig];
            bh2[1] = pBh[nr * LDW + tig + 4];
            bl2[0] = pBl[nr * LDW + tig];
            bl2[1] = pBl[nr * LDW + tig + 4];
            #pragma unroll
            for (int mi = 0; mi < 2; mi++) {
                mma16816(acc[mi][ni], ah[mi], bh2);
                mma16816(acc[mi][ni], ah[mi], bl2);
                mma16816(acc[mi][ni], al[mi], bh2);
            }
        }
        __syncthreads();
    }
    #undef LOAD_TILE

    #pragma unroll
    for (int mi = 0; mi < 2; mi++) {
        int row = bm + wr * 32 + mi * 16 + gid;
        #pragma unroll
        for (int ni = 0; ni < 8; ni++) {
            int col = bn + wc * 64 + ni * 8 + tig * 2;
            float2 v0 = make_float2(acc[mi][ni][0], acc[mi][ni][1]);
            float2 v1 = make_float2(acc[mi][ni][2], acc[mi][ni][3]);
            if (MODE == 1) {
                float2 bv = *(const float2*)(bias + col);
                v0.x += bv.x; v0.y += bv.y;
                v1.x += bv.x; v1.y += bv.y;
            }
            *(float2*)(C + (size_t)row * N + col)       = v0;
            *(float2*)(C + (size_t)(row + 8) * N + col) = v1;
        }
    }
}

// ---------------------------------------------------------------------------
// Repack g_qkv -> head-contiguous split operands.
// grid (S/64, B*H), block 256. Q pre-scaled by 1/64. V transposed via smem.
// ---------------------------------------------------------------------------
__global__ __launch_bounds__(256)
void repack_qkv()
{
    __shared__ float vsm[64][65];
    const int tid = threadIdx.x;
    const int bx  = blockIdx.x;     // token tile (64)
    const int bh  = blockIdx.y;
    const int b   = bh >> 4, h = bh & 15;

    const size_t src_base = ((size_t)(b * S_) + bx * 64) * N_QKV + h * 192;
    const size_t qk_dst   = ((size_t)bh * S_ + bx * 64) * HD_;

    #pragma unroll
    for (int i = 0; i < 4; i++) {
        int slot = tid + i * 256;            // 0..1023
        int tok  = slot >> 4;
        int d4   = (slot & 15) << 2;
        const float* src = g_qkv + src_base + (size_t)tok * N_QKV + d4;
        float4 qv = *(const float4*)(src);
        float4 kv = *(const float4*)(src + 64);
        float4 vv = *(const float4*)(src + 128);
        qv.x *= (1.0f/HD_); qv.y *= (1.0f/HD_); qv.z *= (1.0f/HD_); qv.w *= (1.0f/HD_);

        float h0,l0,h1,l1,h2,l2,h3,l3;
        size_t di = qk_dst + (size_t)tok * HD_ + d4;
        split1(qv.x,h0,l0); split1(qv.y,h1,l1); split1(qv.z,h2,l2); split1(qv.w,h3,l3);
        *(uint2*)(g_aq_hi + di) = make_uint2(pack_bf2(h0,h1), pack_bf2(h2,h3));
        *(uint2*)(g_aq_lo + di) = make_uint2(pack_bf2(l0,l1), pack_bf2(l2,l3));
        split1(kv.x,h0,l0); split1(kv.y,h1,l1); split1(kv.z,h2,l2); split1(kv.w,h3,l3);
        *(uint2*)(g_ak_hi + di) = make_uint2(pack_bf2(h0,h1), pack_bf2(h2,h3));
        *(uint2*)(g_ak_lo + di) = make_uint2(pack_bf2(l0,l1), pack_bf2(l2,l3));

        vsm[tok][d4+0] = vv.x; vsm[tok][d4+1] = vv.y;
        vsm[tok][d4+2] = vv.z; vsm[tok][d4+3] = vv.w;
    }
    __syncthreads();

    #pragma unroll
    for (int i = 0; i < 4; i++) {
        int slot = tid + i * 256;
        int dim  = slot >> 4;
        int t4   = (slot & 15) << 2;
        float p0 = vsm[t4+0][dim], p1 = vsm[t4+1][dim];
        float p2 = vsm[t4+2][dim], p3 = vsm[t4+3][dim];
        float h0,l0,h1,l1,h2,l2,h3,l3;
        split1(p0,h0,l0); split1(p1,h1,l1); split1(p2,h2,l2); split1(p3,h3,l3);
        size_t di = ((size_t)bh * HD_ + dim) * S_ + bx * 64 + t4;
        *(uint2*)(g_avt_hi + di) = make_uint2(pack_bf2(h0,h1), pack_bf2(h2,h3));
        *(uint2*)(g_avt_lo + di) = make_uint2(pack_bf2(l0,l1), pack_bf2(l2,l3));
    }
}

// ---------------------------------------------------------------------------
// Tensor-core causal flash attention.
// grid (S/128, B*H), block 256 (8 warps x 16 q-rows). KV tiles of 64 keys,
// cp.async double buffered. bf16x3 split for both QK^T and PV.
// ---------------------------------------------------------------------------
#define ROW_W   36                     // uint32 words per smem row
#define ARR_W   (64 * ROW_W)           // 2304 words per array
#define BUF_W   (4 * ARR_W)            // 9216 words per buffer
#define ATTN_SMEM_BYTES (2 * BUF_W * 4)  // 73728

__global__ __launch_bounds__(256)
void attn_mma()
{
    extern __shared__ uint32_t smw[];
    const int tid  = threadIdx.x;
    const int w    = tid >> 5, lane = tid & 31;
    const int gid  = lane >> 2, tig = lane & 3;
    const int bx   = blockIdx.x, bh = blockIdx.y;
    const int b    = bh >> 4;
    const int h    = bh & 15;
    const int rA   = bx * 128 + w * 16 + gid;   // q row within sequence
    const int rB   = rA + 8;

    // ---- Q fragments (hi/lo), loaded once ----
    const uint32_t* qh_p = (const uint32_t*)(g_aq_hi + ((size_t)bh * S_ + bx*128 + w*16) * HD_);
    const uint32_t* ql_p = (const uint32_t*)(g_aq_lo + ((size_t)bh * S_ + bx*128 + w*16) * HD_);
    uint32_t qh[4][4], ql[4][4];
    #pragma unroll
    for (int kc = 0; kc < 4; kc++) {
        int w0 = 8*kc + tig;
        qh[kc][0] = qh_p[ gid      * 32 + w0    ];
        qh[kc][1] = qh_p[(gid + 8) * 32 + w0    ];
        qh[kc][2] = qh_p[ gid      * 32 + w0 + 4];
        qh[kc][3] = qh_p[(gid + 8) * 32 + w0 + 4];
        ql[kc][0] = ql_p[ gid      * 32 + w0    ];
        ql[kc][1] = ql_p[(gid + 8) * 32 + w0    ];
        ql[kc][2] = ql_p[ gid      * 32 + w0 + 4];
        ql[kc][3] = ql_p[(gid + 8) * 32 + w0 + 4];
    }

    float o[8][4] = {};
    float mA = -INFINITY, mB = -INFINITY, lA = 0.f, lB = 0.f;

    const __nv_bfloat16* kh_p = g_ak_hi  + (size_t)bh * S_ * HD_;
    const __nv_bfloat16* kl_p = g_ak_lo  + (size_t)bh * S_ * HD_;
    const __nv_bfloat16* vh_p = g_avt_hi + (size_t)bh * HD_ * S_;
    const __nv_bfloat16* vl_p = g_avt_lo + (size_t)bh * HD_ * S_;

    const uint32_t sb = (uint32_t)__cvta_generic_to_shared(smw);
    const int lr  = tid >> 3;     // 0..31
    const int seg = tid & 7;

    #define LOAD_KV(T, BUF) do {                                                \
        _Pragma("unroll")                                                       \
        for (int i = 0; i < 8; i++) {                                           \
            int arr = i >> 1;                                                   \
            int r   = (i & 1) * 32 + lr;                                        \
            uint32_t dst = sb + ((BUF)*BUF_W + arr*ARR_W + r*ROW_W + seg*4)*4;  \
            const __nv_bfloat16* srcp;                                          \
            if      (arr == 0) srcp = kh_p + (size_t)((T)*64 + r) * HD_ + seg*8;\
            else if (arr == 1) srcp = kl_p + (size_t)((T)*64 + r) * HD_ + seg*8;\
            else if (arr == 2) srcp = vh_p + (size_t)r * S_ + (T)*64 + seg*8;   \
            else               srcp = vl_p + (size_t)r * S_ + (T)*64 + seg*8;   \
            asm volatile("cp.async.cg.shared.global [%0], [%1], 16;\n"          \
                :: "r"(dst), "l"(srcp));                                        \
        }                                                                       \
        asm volatile("cp.async.commit_group;\n");                               \
    } while (0)

    const int nt = 2 * (bx + 1);
    LOAD_KV(0, 0);

    for (int t = 0; t < nt; t++) {
        const int buf = t & 1;
        if (t + 1 < nt) {
            LOAD_KV(t + 1, (t + 1) & 1);
            asm volatile("cp.async.wait_group 1;\n");
        } else {
            asm volatile("cp.async.wait_group 0;\n");
        }
        __syncthreads();

        const uint32_t* KH = smw + buf * BUF_W;
        const uint32_t* KL = KH + ARR_W;
        const uint32_t* VH = KL + ARR_W;
        const uint32_t* VL = VH + ARR_W;

        // ---- S = Q @ K^T (scaled q already) ----
        float s[8][4];
        #pragma unroll
        for (int ni = 0; ni < 8; ni++) { s[ni][0]=0; s[ni][1]=0; s[ni][2]=0; s[ni][3]=0; }
        #pragma unroll
        for (int ni = 0; ni < 8; ni++) {
            int nb = (ni * 8 + gid) * ROW_W;
            #pragma unroll
            for (int kc = 0; kc < 4; kc++) {
                uint32_t bh2[2], bl2[2];
                bh2[0] = KH[nb + 8*kc + tig];     bh2[1] = KH[nb + 8*kc + tig + 4];
                bl2[0] = KL[nb + 8*kc + tig];     bl2[1] = KL[nb + 8*kc + tig + 4];
                mma16816(s[ni], qh[kc], bh2);
                mma16816(s[ni], qh[kc], bl2);
                mma16816(s[ni], ql[kc], bh2);
            }
        }

        // ---- causal mask (only the two diagonal tiles need it) ----
        if (t >= 2 * bx) {
            #pragma unroll
            for (int ni = 0; ni < 8; ni++) {
                int c0 = t * 64 + ni * 8 + 2 * tig;
                if (c0     > rA) s[ni][0] = -1e30f;
                if (c0 + 1 > rA) s[ni][1] = -1e30f;
                if (c0     > rB) s[ni][2] = -1e30f;
                if (c0 + 1 > rB) s[ni][3] = -1e30f;
            }
        }

        // ---- online softmax ----
        float tmA = -INFINITY, tmB = -INFINITY;
        #pragma unroll
        for (int ni = 0; ni < 8; ni++) {
            tmA = fmaxf(tmA, fmaxf(s[ni][0], s[ni][1]));
            tmB = fmaxf(tmB, fmaxf(s[ni][2], s[ni][3]));
        }
        tmA = fmaxf(tmA, __shfl_xor_sync(0xffffffffu, tmA, 1));
        tmA = fmaxf(tmA, __shfl_xor_sync(0xffffffffu, tmA, 2));
        tmB = fmaxf(tmB, __shfl_xor_sync(0xffffffffu, tmB, 1));
        tmB = fmaxf(tmB, __shfl_xor_sync(0xffffffffu, tmB, 2));

        float mnA = fmaxf(mA, tmA), mnB = fmaxf(mB, tmB);
        float sfA = __expf(mA - mnA), sfB = __expf(mB - mnB);
        float lsA = 0.f, lsB = 0.f;

        uint32_t ph[4][4], pl[4][4];
        #pragma unroll
        for (int ni = 0; ni < 8; ni++) {
            float e0 = __expf(s[ni][0] - mnA);
            float e1 = __expf(s[ni][1] - mnA);
            float e2 = __expf(s[ni][2] - mnB);
            float e3 = __expf(s[ni][3] - mnB);
            lsA += e0 + e1;  lsB += e2 + e3;
            float h0,l0,h1,l1,h2,l2,h3,l3;
            split1(e0,h0,l0); split1(e1,h1,l1); split1(e2,h2,l2); split1(e3,h3,l3);
            int kc = ni >> 1, off = (ni & 1) * 2;
            ph[kc][off]     = pack_bf2(h0, h1);
            ph[kc][off + 1] = pack_bf2(h2, h3);
            pl[kc][off]     = pack_bf2(l0, l1);
            pl[kc][off + 1] = pack_bf2(l2, l3);
        }
        lsA += __shfl_xor_sync(0xffffffffu, lsA, 1);
        lsA += __shfl_xor_sync(0xffffffffu, lsA, 2);
        lsB += __shfl_xor_sync(0xffffffffu, lsB, 1);
        lsB += __shfl_xor_sync(0xffffffffu, lsB, 2);

        mA = mnA; mB = mnB;
        lA = lA * sfA + lsA;
        lB = lB * sfB + lsB;

        #pragma unroll
        for (int nd = 0; nd < 8; nd++) {
            o[nd][0] *= sfA; o[nd][1] *= sfA;
            o[nd][2] *= sfB; o[nd][3] *= sfB;
        }

        // ---- O += P @ V ----
        #pragma unroll
        for (int nd = 0; nd < 8; nd++) {
            int nb = (nd * 8 + gid) * ROW_W;
            #pragma unroll
            for (int kc = 0; kc < 4; kc++) {
                uint32_t vh2[2], vl2[2];
                vh2[0] = VH[nb + 8*kc + tig];     vh2[1] = VH[nb + 8*kc + tig + 4];
                vl2[0] = VL[nb + 8*kc + tig];     vl2[1] = VL[nb + 8*kc + tig + 4];
                mma16816(o[nd], ph[kc], vh2);
                mma16816(o[nd], ph[kc], vl2);
                mma16816(o[nd], pl[kc], vh2);
            }
        }
        __syncthreads();
    }
    #undef LOAD_KV

    // ---- epilogue: normalize, split to bf16 hi/lo, write [B*S, 1024] ----
    // NOTE: global row includes the batch offset b*S_ (R5 bug was missing it).
    const float iA = 1.0f / lA, iB = 1.0f / lB;
    const size_t gRowA = (size_t)(b * S_ + rA);
    const size_t gRowB = (size_t)(b * S_ + rB);
    #pragma unroll
    for (int nd = 0; nd < 8; nd++) {
        float v0 = o[nd][0] * iA, v1 = o[nd][1] * iA;
        float v2 = o[nd][2] * iB, v3 = o[nd][3] * iB;
        float h0,l0,h1,l1,h2,l2,h3,l3;
        split1(v0,h0,l0); split1(v1,h1,l1); split1(v2,h2,l2); split1(v3,h3,l3);
        size_t i0 = gRowA * D_ + h * HD_ + nd * 8 + 2 * tig;
        size_t i1 = gRowB * D_ + h * HD_ + nd * 8 + 2 * tig;
        *(uint32_t*)(g_at_hi + i0) = pack_bf2(h0, h1);
        *(uint32_t*)(g_at_lo + i0) = pack_bf2(l0, l1);
        *(uint32_t*)(g_at_hi + i1) = pack_bf2(h2, h3);
        *(uint32_t*)(g_at_lo + i1) = pack_bf2(l2, l3);
    }
}

// ---------------------------------------------------------------------------
extern "C" void kernel_launch(void* const* d_in, const int* in_sizes, int n_in,
                              void* d_out, int out_size)
{
    const float* x = nullptr, *w_qkv = nullptr, *w_out = nullptr, *b_out = nullptr;
    for (int i = 0; i < n_in; i++) {
        long long n = in_sizes[i];
        if      (n == (long long)B_ * S_ * D_)      x     = (const float*)d_in[i];
        else if (n == (long long)N_QKV * D_)        w_qkv = (const float*)d_in[i];
        else if (n == (long long)D_ * D_)           w_out = (const float*)d_in[i];
        else if (n == (long long)D_)                b_out = (const float*)d_in[i];
        // mask ignored: causality is static
    }
    float* out = (float*)d_out;

    cudaFuncSetAttribute(attn_mma, cudaFuncAttributeMaxDynamicSharedMemorySize,
                         ATTN_SMEM_BYTES);

    // 0) Split GEMM inputs into bf16 hi/lo
    split_bf16<0><<<4096, 256>>>(x,     (M_TOT * D_) / 4);
    split_bf16<1><<<3072, 256>>>(w_qkv, (N_QKV * D_) / 4);
    split_bf16<2><<<1024, 256>>>(w_out, (D_ * D_) / 4);

    // 1) QKV projection: g_qkv = x @ w_qkv^T
    gemm_bf16x3<0><<<dim3(N_QKV / 128, M_TOT / 128), 256>>>(
        nullptr, nullptr, M_TOT, N_QKV, D_);

    // 2) Repack to head-contiguous split operands (q/64, K, V^T)
    repack_qkv<<<dim3(S_ / 64, B_ * H_), 256>>>();

    // 3) Tensor-core causal flash attention -> g_at_hi/lo
    attn_mma<<<dim3(S_ / 128, B_ * H_), 256, ATTN_SMEM_BYTES>>>();

    // 4) Output projection: out = attn @ w_out^T + b_out
    gemm_bf16x3<1><<<dim3(D_ / 128, M_TOT / 128), 256>>>(
        b_out, out, M_TOT, D_, D_);
}

// round 7
// speedup vs baseline: 2.9429x; 1.1603x over previous
#include <cuda_runtime.h>
#include <cuda_bf16.h>
#include <stdint.h>
#include <math.h>

// Problem constants
#define B_   2
#define S_   2048
#define D_   1024
#define H_   16
#define HD_  64
#define M_TOT (B_*S_)     // 4096
#define N_QKV (3*D_)      // 3072

// ---------------------------------------------------------------------------
// Scratch (allocation-free rule: __device__ globals)
// ---------------------------------------------------------------------------
__device__ float g_qkv [(size_t)M_TOT * N_QKV];  // [B*S, 3*D]

// bf16 hi/lo split operands for the projection GEMMs
__device__ __nv_bfloat16 g_x_hi [(size_t)M_TOT * D_];
__device__ __nv_bfloat16 g_x_lo [(size_t)M_TOT * D_];
__device__ __nv_bfloat16 g_wq_hi[(size_t)N_QKV * D_];
__device__ __nv_bfloat16 g_wq_lo[(size_t)N_QKV * D_];
__device__ __nv_bfloat16 g_at_hi[(size_t)M_TOT * D_];   // attention out (split)
__device__ __nv_bfloat16 g_at_lo[(size_t)M_TOT * D_];
__device__ __nv_bfloat16 g_wo_hi[(size_t)D_ * D_];
__device__ __nv_bfloat16 g_wo_lo[(size_t)D_ * D_];

// Head-contiguous attention operands (split), from repack kernel
__device__ __nv_bfloat16 g_aq_hi [(size_t)B_*H_*S_*HD_];  // [bh][S][64], q/64
__device__ __nv_bfloat16 g_aq_lo [(size_t)B_*H_*S_*HD_];
__device__ __nv_bfloat16 g_ak_hi [(size_t)B_*H_*S_*HD_];  // [bh][S][64]
__device__ __nv_bfloat16 g_ak_lo [(size_t)B_*H_*S_*HD_];
__device__ __nv_bfloat16 g_avt_hi[(size_t)B_*H_*HD_*S_];  // [bh][64][S]  (V^T)
__device__ __nv_bfloat16 g_avt_lo[(size_t)B_*H_*HD_*S_];

// ---------------------------------------------------------------------------
// helpers
// ---------------------------------------------------------------------------
__device__ __forceinline__ uint32_t pack_bf2(float lo, float hi) {
    __nv_bfloat162 t = __floats2bfloat162_rn(lo, hi);   // .x = lo half
    return *(uint32_t*)&t;
}
__device__ __forceinline__ void split1(float v, float& h, float& l) {
    __nv_bfloat16 hb = __float2bfloat16_rn(v);
    h = __bfloat162float(hb);
    l = v - h;
}

__device__ __forceinline__ void mma16816(float* c, const uint32_t* a, const uint32_t* b)
{
    asm volatile(
        "mma.sync.aligned.m16n8k16.row.col.f32.bf16.bf16.f32 "
        "{%0,%1,%2,%3}, {%4,%5,%6,%7}, {%8,%9}, {%0,%1,%2,%3};\n"
        : "+f"(c[0]), "+f"(c[1]), "+f"(c[2]), "+f"(c[3])
        : "r"(a[0]), "r"(a[1]), "r"(a[2]), "r"(a[3]), "r"(b[0]), "r"(b[1]));
}

__device__ __forceinline__ void ldsm_x4(uint32_t* r, uint32_t addr)
{
    asm volatile(
        "ldmatrix.sync.aligned.m8n8.x4.shared.b16 {%0,%1,%2,%3}, [%4];\n"
        : "=r"(r[0]), "=r"(r[1]), "=r"(r[2]), "=r"(r[3]) : "r"(addr));
}

// ---------------------------------------------------------------------------
// Elementwise split for GEMM inputs: a -> (hi, lo)
// ---------------------------------------------------------------------------
template<int ID>
__global__ void split_bf16(const float* __restrict__ src, int n4)
{
    __nv_bfloat16* hi = (ID == 0) ? g_x_hi : (ID == 1) ? g_wq_hi : g_wo_hi;
    __nv_bfloat16* lo = (ID == 0) ? g_x_lo : (ID == 1) ? g_wq_lo : g_wo_lo;

    for (int i = blockIdx.x * blockDim.x + threadIdx.x; i < n4;
         i += gridDim.x * blockDim.x) {
        float4 v = ((const float4*)src)[i];
        float h0,l0,h1,l1,h2,l2,h3,l3;
        split1(v.x,h0,l0); split1(v.y,h1,l1); split1(v.z,h2,l2); split1(v.w,h3,l3);
        ((uint32_t*)hi)[2*i + 0] = pack_bf2(h0, h1);
        ((uint32_t*)hi)[2*i + 1] = pack_bf2(h2, h3);
        ((uint32_t*)lo)[2*i + 0] = pack_bf2(l0, l1);
        ((uint32_t*)lo)[2*i + 1] = pack_bf2(l2, l3);
    }
}

// ---------------------------------------------------------------------------
// bf16x3-split tensor-core NT GEMM: C[M,N] = A[M,K] @ B[N,K]^T (+ bias)
// Tile BM=128, BN=128, BK=32; 8 warps (4x2), warp tile 32x64.
// 2-stage cp.async pipeline; all fragments via ldmatrix.x4.
// smem layout per stage: 4 arrays (Ah,Al,Bh,Bl) x 128 rows x 20 words
// (16 data + 4 pad; 20r mod 32 distinct for r=0..7 -> ldmatrix conflict-free).
// ---------------------------------------------------------------------------
#define GLDW 20
#define GARR (128 * GLDW)           // words per array
#define GSTG (4 * GARR)             // words per stage
#define GEMM_SMEM_BYTES (2 * GSTG * 4)   // 81920

template<int MODE>
__global__ __launch_bounds__(256, 2)
void gemm_bf16x3(const float* __restrict__ bias, float* __restrict__ C_out,
                 int M, int N, int K)
{
    extern __shared__ uint32_t gsm[];

    const __nv_bfloat16 *Ah, *Al, *Bh, *Bl;
    float* C;
    if (MODE == 0) { Ah = g_x_hi;  Al = g_x_lo;  Bh = g_wq_hi; Bl = g_wq_lo; C = g_qkv; }
    else           { Ah = g_at_hi; Al = g_at_lo; Bh = g_wo_hi; Bl = g_wo_lo; C = C_out; }

    const int tid  = threadIdx.x;
    const int lane = tid & 31;
    const int warp = tid >> 5;
    const int wr = warp >> 1, wc = warp & 1;
    const int gid = lane >> 2, tig = lane & 3;

    const int bm = blockIdx.y * 128;
    const int bn = blockIdx.x * 128;

    // cp.async loader: 4 threads per row (16B chunks), 2 row-halves per array
    const int lrow   = tid >> 2;          // 0..63
    const int lchunk = tid & 3;           // 16B chunk -> bf16 offset lchunk*8

    const uint32_t sb = (uint32_t)__cvta_generic_to_shared(gsm);

    #define G_LOAD(T, S) do {                                                   \
        int k0_ = (T) * 32;                                                     \
        _Pragma("unroll")                                                       \
        for (int hh = 0; hh < 2; hh++) {                                        \
            int row = lrow + hh * 64;                                           \
            uint32_t d0 = sb + (uint32_t)((S)*GSTG + row*GLDW + lchunk*4) * 4;  \
            size_t asrc = (size_t)(bm + row) * K + k0_ + lchunk*8;              \
            size_t bsrc = (size_t)(bn + row) * K + k0_ + lchunk*8;              \
            asm volatile("cp.async.cg.shared.global [%0], [%1], 16;\n"          \
                :: "r"(d0),              "l"(Ah + asrc));                       \
            asm volatile("cp.async.cg.shared.global [%0], [%1], 16;\n"          \
                :: "r"(d0 + GARR*4),     "l"(Al + asrc));                       \
            asm volatile("cp.async.cg.shared.global [%0], [%1], 16;\n"          \
                :: "r"(d0 + 2*GARR*4),   "l"(Bh + bsrc));                       \
            asm volatile("cp.async.cg.shared.global [%0], [%1], 16;\n"          \
                :: "r"(d0 + 3*GARR*4),   "l"(Bl + bsrc));                       \
        }                                                                       \
        asm volatile("cp.async.commit_group;\n");                               \
    } while (0)

    // ldmatrix byte offsets (within an array; add kcb*32 and stage/array base)
    uint32_t a_off[2], b_off[4];
    #pragma unroll
    for (int mi = 0; mi < 2; mi++)
        a_off[mi] = (uint32_t)((wr*32 + mi*16 + (lane & 15)) * GLDW * 4
                               + (lane >> 4) * 16);
    #pragma unroll
    for (int np = 0; np < 4; np++)
        b_off[np] = (uint32_t)((wc*64 + np*16 + ((lane >> 4) & 1)*8 + (lane & 7))
                               * GLDW * 4 + ((lane >> 3) & 1) * 16);

    float acc[2][8][4] = {};

    const int nt = K / 32;
    G_LOAD(0, 0);

    for (int t = 0; t < nt; t++) {
        const int stg = t & 1;
        if (t + 1 < nt) {
            G_LOAD(t + 1, (t + 1) & 1);
            asm volatile("cp.async.wait_group 1;\n");
        } else {
            asm volatile("cp.async.wait_group 0;\n");
        }
        __syncthreads();

        const uint32_t sAh = sb + (uint32_t)(stg * GSTG) * 4;
        const uint32_t sAl = sAh + GARR * 4;
        const uint32_t sBh = sAh + 2 * GARR * 4;
        const uint32_t sBl = sAh + 3 * GARR * 4;

        #pragma unroll
        for (int kcb = 0; kcb < 2; kcb++) {
            uint32_t ah[2][4], al[2][4];
            ldsm_x4(ah[0], sAh + a_off[0] + kcb*32);
            ldsm_x4(ah[1], sAh + a_off[1] + kcb*32);
            ldsm_x4(al[0], sAl + a_off[0] + kcb*32);
            ldsm_x4(al[1], sAl + a_off[1] + kcb*32);
            #pragma unroll
            for (int np = 0; np < 4; np++) {
                uint32_t bhf[4], blf[4];
                ldsm_x4(bhf, sBh + b_off[np] + kcb*32);
                ldsm_x4(blf, sBl + b_off[np] + kcb*32);
                #pragma unroll
                for (int sub = 0; sub < 2; sub++) {
                    int ni = np * 2 + sub;
                    #pragma unroll
                    for (int mi = 0; mi < 2; mi++) {
                        mma16816(acc[mi][ni], ah[mi], bhf + sub*2);
                        mma16816(acc[mi][ni], ah[mi], blf + sub*2);
                        mma16816(acc[mi][ni], al[mi], bhf + sub*2);
                    }
                }
            }
        }
        __syncthreads();
    }
    #undef G_LOAD

    #pragma unroll
    for (int mi = 0; mi < 2; mi++) {
        int row = bm + wr * 32 + mi * 16 + gid;
        #pragma unroll
        for (int ni = 0; ni < 8; ni++) {
            int col = bn + wc * 64 + ni * 8 + tig * 2;
            float2 v0 = make_float2(acc[mi][ni][0], acc[mi][ni][1]);
            float2 v1 = make_float2(acc[mi][ni][2], acc[mi][ni][3]);
            if (MODE == 1) {
                float2 bv = *(const float2*)(bias + col);
                v0.x += bv.x; v0.y += bv.y;
                v1.x += bv.x; v1.y += bv.y;
            }
            *(float2*)(C + (size_t)row * N + col)       = v0;
            *(float2*)(C + (size_t)(row + 8) * N + col) = v1;
        }
    }
}

// ---------------------------------------------------------------------------
// Repack g_qkv -> head-contiguous split operands (unchanged from R6).
// ---------------------------------------------------------------------------
__global__ __launch_bounds__(256)
void repack_qkv()
{
    __shared__ float vsm[64][65];
    const int tid = threadIdx.x;
    const int bx  = blockIdx.x;
    const int bh  = blockIdx.y;
    const int b   = bh >> 4, h = bh & 15;

    const size_t src_base = ((size_t)(b * S_) + bx * 64) * N_QKV + h * 192;
    const size_t qk_dst   = ((size_t)bh * S_ + bx * 64) * HD_;

    #pragma unroll
    for (int i = 0; i < 4; i++) {
        int slot = tid + i * 256;
        int tok  = slot >> 4;
        int d4   = (slot & 15) << 2;
        const float* src = g_qkv + src_base + (size_t)tok * N_QKV + d4;
        float4 qv = *(const float4*)(src);
        float4 kv = *(const float4*)(src + 64);
        float4 vv = *(const float4*)(src + 128);
        qv.x *= (1.0f/HD_); qv.y *= (1.0f/HD_); qv.z *= (1.0f/HD_); qv.w *= (1.0f/HD_);

        float h0,l0,h1,l1,h2,l2,h3,l3;
        size_t di = qk_dst + (size_t)tok * HD_ + d4;
        split1(qv.x,h0,l0); split1(qv.y,h1,l1); split1(qv.z,h2,l2); split1(qv.w,h3,l3);
        *(uint2*)(g_aq_hi + di) = make_uint2(pack_bf2(h0,h1), pack_bf2(h2,h3));
        *(uint2*)(g_aq_lo + di) = make_uint2(pack_bf2(l0,l1), pack_bf2(l2,l3));
        split1(kv.x,h0,l0); split1(kv.y,h1,l1); split1(kv.z,h2,l2); split1(kv.w,h3,l3);
        *(uint2*)(g_ak_hi + di) = make_uint2(pack_bf2(h0,h1), pack_bf2(h2,h3));
        *(uint2*)(g_ak_lo + di) = make_uint2(pack_bf2(l0,l1), pack_bf2(l2,l3));

        vsm[tok][d4+0] = vv.x; vsm[tok][d4+1] = vv.y;
        vsm[tok][d4+2] = vv.z; vsm[tok][d4+3] = vv.w;
    }
    __syncthreads();

    #pragma unroll
    for (int i = 0; i < 4; i++) {
        int slot = tid + i * 256;
        int dim  = slot >> 4;
        int t4   = (slot & 15) << 2;
        float p0 = vsm[t4+0][dim], p1 = vsm[t4+1][dim];
        float p2 = vsm[t4+2][dim], p3 = vsm[t4+3][dim];
        float h0,l0,h1,l1,h2,l2,h3,l3;
        split1(p0,h0,l0); split1(p1,h1,l1); split1(p2,h2,l2); split1(p3,h3,l3);
        size_t di = ((size_t)bh * HD_ + dim) * S_ + bx * 64 + t4;
        *(uint2*)(g_avt_hi + di) = make_uint2(pack_bf2(h0,h1), pack_bf2(h2,h3));
        *(uint2*)(g_avt_lo + di) = make_uint2(pack_bf2(l0,l1), pack_bf2(l2,l3));
    }
}

// ---------------------------------------------------------------------------
// Tensor-core causal flash attention (R6 logic, fragments via ldmatrix.x4).
// ROW_W=36: 36r mod 32 distinct over r=0..7 -> ldmatrix conflict-free.
// ---------------------------------------------------------------------------
#define ROW_W   36
#define ARR_W   (64 * ROW_W)
#define BUF_W   (4 * ARR_W)
#define ATTN_SMEM_BYTES (2 * BUF_W * 4)  // 73728

__global__ __launch_bounds__(256)
void attn_mma()
{
    extern __shared__ uint32_t smw[];
    const int tid  = threadIdx.x;
    const int w    = tid >> 5, lane = tid & 31;
    const int gid  = lane >> 2, tig = lane & 3;
    const int bx   = blockIdx.x, bh = blockIdx.y;
    const int b    = bh >> 4;
    const int h    = bh & 15;
    const int rA   = bx * 128 + w * 16 + gid;
    const int rB   = rA + 8;

    // ---- Q fragments (hi/lo), loaded once ----
    const uint32_t* qh_p = (const uint32_t*)(g_aq_hi + ((size_t)bh * S_ + bx*128 + w*16) * HD_);
    const uint32_t* ql_p = (const uint32_t*)(g_aq_lo + ((size_t)bh * S_ + bx*128 + w*16) * HD_);
    uint32_t qh[4][4], ql[4][4];
    #pragma unroll
    for (int kc = 0; kc < 4; kc++) {
        int w0 = 8*kc + tig;
        qh[kc][0] = qh_p[ gid      * 32 + w0    ];
        qh[kc][1] = qh_p[(gid + 8) * 32 + w0    ];
        qh[kc][2] = qh_p[ gid      * 32 + w0 + 4];
        qh[kc][3] = qh_p[(gid + 8) * 32 + w0 + 4];
        ql[kc][0] = ql_p[ gid      * 32 + w0    ];
        ql[kc][1] = ql_p[(gid + 8) * 32 + w0    ];
        ql[kc][2] = ql_p[ gid      * 32 + w0 + 4];
        ql[kc][3] = ql_p[(gid + 8) * 32 + w0 + 4];
    }

    float o[8][4] = {};
    float mA = -INFINITY, mB = -INFINITY, lA = 0.f, lB = 0.f;

    const __nv_bfloat16* kh_p = g_ak_hi  + (size_t)bh * S_ * HD_;
    const __nv_bfloat16* kl_p = g_ak_lo  + (size_t)bh * S_ * HD_;
    const __nv_bfloat16* vh_p = g_avt_hi + (size_t)bh * HD_ * S_;
    const __nv_bfloat16* vl_p = g_avt_lo + (size_t)bh * HD_ * S_;

    const uint32_t sb = (uint32_t)__cvta_generic_to_shared(smw);
    const int lr  = tid >> 3;
    const int seg = tid & 7;

    // ldmatrix byte offset within an array: 4 tiles (kc,kc k+8,kc+1,kc+1 k+8)
    const uint32_t frag_off = (uint32_t)((lane & 7) * ROW_W * 4 + (lane >> 3) * 16);

    #define LOAD_KV(T, BUF) do {                                                \
        _Pragma("unroll")                                                       \
        for (int i = 0; i < 8; i++) {                                           \
            int arr = i >> 1;                                                   \
            int r   = (i & 1) * 32 + lr;                                        \
            uint32_t dst = sb + ((BUF)*BUF_W + arr*ARR_W + r*ROW_W + seg*4)*4;  \
            const __nv_bfloat16* srcp;                                          \
            if      (arr == 0) srcp = kh_p + (size_t)((T)*64 + r) * HD_ + seg*8;\
            else if (arr == 1) srcp = kl_p + (size_t)((T)*64 + r) * HD_ + seg*8;\
            else if (arr == 2) srcp = vh_p + (size_t)r * S_ + (T)*64 + seg*8;   \
            else               srcp = vl_p + (size_t)r * S_ + (T)*64 + seg*8;   \
            asm volatile("cp.async.cg.shared.global [%0], [%1], 16;\n"          \
                :: "r"(dst), "l"(srcp));                                        \
        }                                                                       \
        asm volatile("cp.async.commit_group;\n");                               \
    } while (0)

    const int nt = 2 * (bx + 1);
    LOAD_KV(0, 0);

    for (int t = 0; t < nt; t++) {
        const int buf = t & 1;
        if (t + 1 < nt) {
            LOAD_KV(t + 1, (t + 1) & 1);
            asm volatile("cp.async.wait_group 1;\n");
        } else {
            asm volatile("cp.async.wait_group 0;\n");
        }
        __syncthreads();

        const uint32_t sKH = sb + (uint32_t)(buf * BUF_W) * 4;
        const uint32_t sKL = sKH + ARR_W * 4;
        const uint32_t sVH = sKH + 2 * ARR_W * 4;
        const uint32_t sVL = sKH + 3 * ARR_W * 4;

        // ---- S = Q @ K^T ----
        float s[8][4];
        #pragma unroll
        for (int ni = 0; ni < 8; ni++) { s[ni][0]=0; s[ni][1]=0; s[ni][2]=0; s[ni][3]=0; }
        #pragma unroll
        for (int ni = 0; ni < 8; ni++) {
            uint32_t off = (uint32_t)(ni * 8 * ROW_W * 4) + frag_off;
            #pragma unroll
            for (int kp = 0; kp < 2; kp++) {
                uint32_t bh4[4], bl4[4];
                ldsm_x4(bh4, sKH + off + kp*64);
                ldsm_x4(bl4, sKL + off + kp*64);
                mma16816(s[ni], qh[2*kp],   bh4);
                mma16816(s[ni], qh[2*kp],   bl4);
                mma16816(s[ni], ql[2*kp],   bh4);
                mma16816(s[ni], qh[2*kp+1], bh4 + 2);
                mma16816(s[ni], qh[2*kp+1], bl4 + 2);
                mma16816(s[ni], ql[2*kp+1], bh4 + 2);
            }
        }

        // ---- causal mask (only diagonal tiles) ----
        if (t >= 2 * bx) {
            #pragma unroll
            for (int ni = 0; ni < 8; ni++) {
                int c0 = t * 64 + ni * 8 + 2 * tig;
                if (c0     > rA) s[ni][0] = -1e30f;
                if (c0 + 1 > rA) s[ni][1] = -1e30f;
                if (c0     > rB) s[ni][2] = -1e30f;
                if (c0 + 1 > rB) s[ni][3] = -1e30f;
            }
        }

        // ---- online softmax ----
        float tmA = -INFINITY, tmB = -INFINITY;
        #pragma unroll
        for (int ni = 0; ni < 8; ni++) {
            tmA = fmaxf(tmA, fmaxf(s[ni][0], s[ni][1]));
            tmB = fmaxf(tmB, fmaxf(s[ni][2], s[ni][3]));
        }
        tmA = fmaxf(tmA, __shfl_xor_sync(0xffffffffu, tmA, 1));
        tmA = fmaxf(tmA, __shfl_xor_sync(0xffffffffu, tmA, 2));
        tmB = fmaxf(tmB, __shfl_xor_sync(0xffffffffu, tmB, 1));
        tmB = fmaxf(tmB, __shfl_xor_sync(0xffffffffu, tmB, 2));

        float mnA = fmaxf(mA, tmA), mnB = fmaxf(mB, tmB);
        float sfA = __expf(mA - mnA), sfB = __expf(mB - mnB);
        float lsA = 0.f, lsB = 0.f;

        uint32_t ph[4][4], pl[4][4];
        #pragma unroll
        for (int ni = 0; ni < 8; ni++) {
            float e0 = __expf(s[ni][0] - mnA);
            float e1 = __expf(s[ni][1] - mnA);
            float e2 = __expf(s[ni][2] - mnB);
            float e3 = __expf(s[ni][3] - mnB);
            lsA += e0 + e1;  lsB += e2 + e3;
            float h0,l0,h1,l1,h2,l2,h3,l3;
            split1(e0,h0,l0); split1(e1,h1,l1); split1(e2,h2,l2); split1(e3,h3,l3);
            int kc = ni >> 1, off = (ni & 1) * 2;
            ph[kc][off]     = pack_bf2(h0, h1);
            ph[kc][off + 1] = pack_bf2(h2, h3);
            pl[kc][off]     = pack_bf2(l0, l1);
            pl[kc][off + 1] = pack_bf2(l2, l3);
        }
        lsA += __shfl_xor_sync(0xffffffffu, lsA, 1);
        lsA += __shfl_xor_sync(0xffffffffu, lsA, 2);
        lsB += __shfl_xor_sync(0xffffffffu, lsB, 1);
        lsB += __shfl_xor_sync(0xffffffffu, lsB, 2);

        mA = mnA; mB = mnB;
        lA = lA * sfA + lsA;
        lB = lB * sfB + lsB;

        #pragma unroll
        for (int nd = 0; nd < 8; nd++) {
            o[nd][0] *= sfA; o[nd][1] *= sfA;
            o[nd][2] *= sfB; o[nd][3] *= sfB;
        }

        // ---- O += P @ V ----
        #pragma unroll
        for (int nd = 0; nd < 8; nd++) {
            uint32_t off = (uint32_t)(nd * 8 * ROW_W * 4) + frag_off;
            #pragma unroll
            for (int kp = 0; kp < 2; kp++) {
                uint32_t vh4[4], vl4[4];
                ldsm_x4(vh4, sVH + off + kp*64);
                ldsm_x4(vl4, sVL + off + kp*64);
                mma16816(o[nd], ph[2*kp],   vh4);
                mma16816(o[nd], ph[2*kp],   vl4);
                mma16816(o[nd], pl[2*kp],   vh4);
                mma16816(o[nd], ph[2*kp+1], vh4 + 2);
                mma16816(o[nd], ph[2*kp+1], vl4 + 2);
                mma16816(o[nd], pl[2*kp+1], vh4 + 2);
            }
        }
        __syncthreads();
    }
    #undef LOAD_KV

    // ---- epilogue: normalize, split to bf16 hi/lo, write [B*S, 1024] ----
    const float iA = 1.0f / lA, iB = 1.0f / lB;
    const size_t gRowA = (size_t)(b * S_ + rA);
    const size_t gRowB = (size_t)(b * S_ + rB);
    #pragma unroll
    for (int nd = 0; nd < 8; nd++) {
        float v0 = o[nd][0] * iA, v1 = o[nd][1] * iA;
        float v2 = o[nd][2] * iB, v3 = o[nd][3] * iB;
        float h0,l0,h1,l1,h2,l2,h3,l3;
        split1(v0,h0,l0); split1(v1,h1,l1); split1(v2,h2,l2); split1(v3,h3,l3);
        size_t i0 = gRowA * D_ + h * HD_ + nd * 8 + 2 * tig;
        size_t i1 = gRowB * D_ + h * HD_ + nd * 8 + 2 * tig;
        *(uint32_t*)(g_at_hi + i0) = pack_bf2(h0, h1);
        *(uint32_t*)(g_at_lo + i0) = pack_bf2(l0, l1);
        *(uint32_t*)(g_at_hi + i1) = pack_bf2(h2, h3);
        *(uint32_t*)(g_at_lo + i1) = pack_bf2(l2, l3);
    }
}

// ---------------------------------------------------------------------------
extern "C" void kernel_launch(void* const* d_in, const int* in_sizes, int n_in,
                              void* d_out, int out_size)
{
    const float* x = nullptr, *w_qkv = nullptr, *w_out = nullptr, *b_out = nullptr;
    for (int i = 0; i < n_in; i++) {
        long long n = in_sizes[i];
        if      (n == (long long)B_ * S_ * D_)      x     = (const float*)d_in[i];
        else if (n == (long long)N_QKV * D_)        w_qkv = (const float*)d_in[i];
        else if (n == (long long)D_ * D_)           w_out = (const float*)d_in[i];
        else if (n == (long long)D_)                b_out = (const float*)d_in[i];
        // mask ignored: causality is static
    }
    float* out = (float*)d_out;

    cudaFuncSetAttribute(attn_mma, cudaFuncAttributeMaxDynamicSharedMemorySize,
                         ATTN_SMEM_BYTES);
    cudaFuncSetAttribute(gemm_bf16x3<0>, cudaFuncAttributeMaxDynamicSharedMemorySize,
                         GEMM_SMEM_BYTES);
    cudaFuncSetAttribute(gemm_bf16x3<1>, cudaFuncAttributeMaxDynamicSharedMemorySize,
                         GEMM_SMEM_BYTES);

    // 0) Split GEMM inputs into bf16 hi/lo
    split_bf16<0><<<4096, 256>>>(x,     (M_TOT * D_) / 4);
    split_bf16<1><<<3072, 256>>>(w_qkv, (N_QKV * D_) / 4);
    split_bf16<2><<<1024, 256>>>(w_out, (D_ * D_) / 4);

    // 1) QKV projection: g_qkv = x @ w_qkv^T
    gemm_bf16x3<0><<<dim3(N_QKV / 128, M_TOT / 128), 256, GEMM_SMEM_BYTES>>>(
        nullptr, nullptr, M_TOT, N_QKV, D_);

    // 2) Repack to head-contiguous split operands (q/64, K, V^T)
    repack_qkv<<<dim3(S_ / 64, B_ * H_), 256>>>();

    // 3) Tensor-core causal flash attention -> g_at_hi/lo
    attn_mma<<<dim3(S_ / 128, B_ * H_), 256, ATTN_SMEM_BYTES>>>();

    // 4) Output projection: out = attn @ w_out^T + b_out
    gemm_bf16x3<1><<<dim3(D_ / 128, M_TOT / 128), 256, GEMM_SMEM_BYTES>>>(
        b_out, out, M_TOT, D_, D_);
}

// round 9
// speedup vs baseline: 2.9730x; 1.0102x over previous
#include <cuda_runtime.h>
#include <cuda_bf16.h>
#include <stdint.h>
#include <math.h>

// Problem constants
#define B_   2
#define S_   2048
#define D_   1024
#define H_   16
#define HD_  64
#define M_TOT (B_*S_)     // 4096
#define N_QKV (3*D_)      // 3072

// ---------------------------------------------------------------------------
// Scratch (allocation-free rule: __device__ globals)
// NOTE: no fp32 g_qkv anymore — gemm0 writes split attention operands directly.
// ---------------------------------------------------------------------------
__device__ __nv_bfloat16 g_x_hi [(size_t)M_TOT * D_];
__device__ __nv_bfloat16 g_x_lo [(size_t)M_TOT * D_];
__device__ __nv_bfloat16 g_wq_hi[(size_t)N_QKV * D_];
__device__ __nv_bfloat16 g_wq_lo[(size_t)N_QKV * D_];
__device__ __nv_bfloat16 g_at_hi[(size_t)M_TOT * D_];   // attention out (split)
__device__ __nv_bfloat16 g_at_lo[(size_t)M_TOT * D_];
__device__ __nv_bfloat16 g_wo_hi[(size_t)D_ * D_];
__device__ __nv_bfloat16 g_wo_lo[(size_t)D_ * D_];

// Head-contiguous attention operands (split), written by gemm0 epilogue
__device__ __nv_bfloat16 g_aq_hi [(size_t)B_*H_*S_*HD_];  // [bh][S][64], q/64
__device__ __nv_bfloat16 g_aq_lo [(size_t)B_*H_*S_*HD_];
__device__ __nv_bfloat16 g_ak_hi [(size_t)B_*H_*S_*HD_];  // [bh][S][64]
__device__ __nv_bfloat16 g_ak_lo [(size_t)B_*H_*S_*HD_];
__device__ __nv_bfloat16 g_avt_hi[(size_t)B_*H_*HD_*S_];  // [bh][64][S]  (V^T)
__device__ __nv_bfloat16 g_avt_lo[(size_t)B_*H_*HD_*S_];

// ---------------------------------------------------------------------------
// helpers
// ---------------------------------------------------------------------------
__device__ __forceinline__ uint32_t pack_bf2(float lo, float hi) {
    __nv_bfloat162 t = __floats2bfloat162_rn(lo, hi);   // .x = lo half
    return *(uint32_t*)&t;
}
__device__ __forceinline__ void split1(float v, float& h, float& l) {
    __nv_bfloat16 hb = __float2bfloat16_rn(v);
    h = __bfloat162float(hb);
    l = v - h;
}
__device__ __forceinline__ void mma16816(float* c, const uint32_t* a, const uint32_t* b)
{
    asm volatile(
        "mma.sync.aligned.m16n8k16.row.col.f32.bf16.bf16.f32 "
        "{%0,%1,%2,%3}, {%4,%5,%6,%7}, {%8,%9}, {%0,%1,%2,%3};\n"
        : "+f"(c[0]), "+f"(c[1]), "+f"(c[2]), "+f"(c[3])
        : "r"(a[0]), "r"(a[1]), "r"(a[2]), "r"(a[3]), "r"(b[0]), "r"(b[1]));
}
__device__ __forceinline__ void ldsm_x4(uint32_t* r, uint32_t addr)
{
    asm volatile(
        "ldmatrix.sync.aligned.m8n8.x4.shared.b16 {%0,%1,%2,%3}, [%4];\n"
        : "=r"(r[0]), "=r"(r[1]), "=r"(r[2]), "=r"(r[3]) : "r"(addr));
}

// ---------------------------------------------------------------------------
// Elementwise split for GEMM inputs: a -> (hi, lo)
// ---------------------------------------------------------------------------
template<int ID>
__global__ void split_bf16(const float* __restrict__ src, int n4)
{
    __nv_bfloat16* hi = (ID == 0) ? g_x_hi : (ID == 1) ? g_wq_hi : g_wo_hi;
    __nv_bfloat16* lo = (ID == 0) ? g_x_lo : (ID == 1) ? g_wq_lo : g_wo_lo;

    for (int i = blockIdx.x * blockDim.x + threadIdx.x; i < n4;
         i += gridDim.x * blockDim.x) {
        float4 v = ((const float4*)src)[i];
        float h0,l0,h1,l1,h2,l2,h3,l3;
        split1(v.x,h0,l0); split1(v.y,h1,l1); split1(v.z,h2,l2); split1(v.w,h3,l3);
        ((uint32_t*)hi)[2*i + 0] = pack_bf2(h0, h1);
        ((uint32_t*)hi)[2*i + 1] = pack_bf2(h2, h3);
        ((uint32_t*)lo)[2*i + 0] = pack_bf2(l0, l1);
        ((uint32_t*)lo)[2*i + 1] = pack_bf2(l2, l3);
    }
}

// ---------------------------------------------------------------------------
// bf16x3-split tensor-core NT GEMM (R7 mainloop).
// MODE 0: A = x splits, B = w_qkv splits; epilogue FUSES the qkv repack:
//         per column c: h=c/192, r=c%192 -> q (scaled 1/64) -> g_aq[bh][tok][d],
//         k -> g_ak[bh][tok][d], v -> g_avt[bh][d][tok] (transposed 2B stores).
// MODE 1: A = attn splits, B = w_out splits, C = d_out + bias (fp32).
// ---------------------------------------------------------------------------
#define GLDW 20
#define GARR (128 * GLDW)
#define GSTG (4 * GARR)
#define GEMM_SMEM_BYTES (2 * GSTG * 4)   // 81920

template<int MODE>
__global__ __launch_bounds__(256, 2)
void gemm_bf16x3(const float* __restrict__ bias, float* __restrict__ C_out,
                 int M, int N, int K)
{
    extern __shared__ uint32_t gsm[];

    const __nv_bfloat16 *Ah, *Al, *Bh, *Bl;
    if (MODE == 0) { Ah = g_x_hi;  Al = g_x_lo;  Bh = g_wq_hi; Bl = g_wq_lo; }
    else           { Ah = g_at_hi; Al = g_at_lo; Bh = g_wo_hi; Bl = g_wo_lo; }

    const int tid  = threadIdx.x;
    const int lane = tid & 31;
    const int warp = tid >> 5;
    const int wr = warp >> 1, wc = warp & 1;
    const int gid = lane >> 2, tig = lane & 3;

    const int bm = blockIdx.y * 128;
    const int bn = blockIdx.x * 128;

    const int lrow   = tid >> 2;
    const int lchunk = tid & 3;

    const uint32_t sb = (uint32_t)__cvta_generic_to_shared(gsm);

    #define G_LOAD(T, S) do {                                                   \
        int k0_ = (T) * 32;                                                     \
        _Pragma("unroll")                                                       \
        for (int hh = 0; hh < 2; hh++) {                                        \
            int row = lrow + hh * 64;                                           \
            uint32_t d0 = sb + (uint32_t)((S)*GSTG + row*GLDW + lchunk*4) * 4;  \
            size_t asrc = (size_t)(bm + row) * K + k0_ + lchunk*8;              \
            size_t bsrc = (size_t)(bn + row) * K + k0_ + lchunk*8;              \
            asm volatile("cp.async.cg.shared.global [%0], [%1], 16;\n"          \
                :: "r"(d0),              "l"(Ah + asrc));                       \
            asm volatile("cp.async.cg.shared.global [%0], [%1], 16;\n"          \
                :: "r"(d0 + GARR*4),     "l"(Al + asrc));                       \
            asm volatile("cp.async.cg.shared.global [%0], [%1], 16;\n"          \
                :: "r"(d0 + 2*GARR*4),   "l"(Bh + bsrc));                       \
            asm volatile("cp.async.cg.shared.global [%0], [%1], 16;\n"          \
                :: "r"(d0 + 3*GARR*4),   "l"(Bl + bsrc));                       \
        }                                                                       \
        asm volatile("cp.async.commit_group;\n");                               \
    } while (0)

    uint32_t a_off[2], b_off[4];
    #pragma unroll
    for (int mi = 0; mi < 2; mi++)
        a_off[mi] = (uint32_t)((wr*32 + mi*16 + (lane & 15)) * GLDW * 4
                               + (lane >> 4) * 16);
    #pragma unroll
    for (int np = 0; np < 4; np++)
        b_off[np] = (uint32_t)((wc*64 + np*16 + ((lane >> 4) & 1)*8 + (lane & 7))
                               * GLDW * 4 + ((lane >> 3) & 1) * 16);

    float acc[2][8][4] = {};

    const int nt = K / 32;
    G_LOAD(0, 0);

    for (int t = 0; t < nt; t++) {
        const int stg = t & 1;
        if (t + 1 < nt) {
            G_LOAD(t + 1, (t + 1) & 1);
            asm volatile("cp.async.wait_group 1;\n");
        } else {
            asm volatile("cp.async.wait_group 0;\n");
        }
        __syncthreads();

        const uint32_t sAh = sb + (uint32_t)(stg * GSTG) * 4;
        const uint32_t sAl = sAh + GARR * 4;
        const uint32_t sBh = sAh + 2 * GARR * 4;
        const uint32_t sBl = sAh + 3 * GARR * 4;

        #pragma unroll
        for (int kcb = 0; kcb < 2; kcb++) {
            uint32_t ah[2][4], al[2][4];
            ldsm_x4(ah[0], sAh + a_off[0] + kcb*32);
            ldsm_x4(ah[1], sAh + a_off[1] + kcb*32);
            ldsm_x4(al[0], sAl + a_off[0] + kcb*32);
            ldsm_x4(al[1], sAl + a_off[1] + kcb*32);
            #pragma unroll
            for (int np = 0; np < 4; np++) {
                uint32_t bhf[4], blf[4];
                ldsm_x4(bhf, sBh + b_off[np] + kcb*32);
                ldsm_x4(blf, sBl + b_off[np] + kcb*32);
                #pragma unroll
                for (int sub = 0; sub < 2; sub++) {
                    int ni = np * 2 + sub;
                    #pragma unroll
                    for (int mi = 0; mi < 2; mi++) {
                        mma16816(acc[mi][ni], ah[mi], bhf + sub*2);
                        mma16816(acc[mi][ni], ah[mi], blf + sub*2);
                        mma16816(acc[mi][ni], al[mi], bhf + sub*2);
                    }
                }
            }
        }
        __syncthreads();
    }
    #undef G_LOAD

    // ---- Epilogue ----
    if (MODE == 1) {
        #pragma unroll
        for (int mi = 0; mi < 2; mi++) {
            int row = bm + wr * 32 + mi * 16 + gid;
            #pragma unroll
            for (int ni = 0; ni < 8; ni++) {
                int col = bn + wc * 64 + ni * 8 + tig * 2;
                float2 bv = *(const float2*)(bias + col);
                float2 v0 = make_float2(acc[mi][ni][0] + bv.x, acc[mi][ni][1] + bv.y);
                float2 v1 = make_float2(acc[mi][ni][2] + bv.x, acc[mi][ni][3] + bv.y);
                *(float2*)(C_out + (size_t)row * N + col)       = v0;
                *(float2*)(C_out + (size_t)(row + 8) * N + col) = v1;
            }
        }
    } else {
        // Fused qkv repack: split fp32 acc directly into attention operands.
        #pragma unroll
        for (int mi = 0; mi < 2; mi++) {
            const int row  = bm + wr * 32 + mi * 16 + gid;   // block never crosses batch
            const int bidx = row >> 11;                       // batch
            const int tokA = row & 2047;
            const int tokB = tokA + 8;
            #pragma unroll
            for (int ni = 0; ni < 8; ni++) {
                int col = bn + wc * 64 + ni * 8 + tig * 2;
                int h   = col / 192;
                int r   = col - h * 192;
                int bh  = bidx * H_ + h;
                float v0 = acc[mi][ni][0], v1 = acc[mi][ni][1];   // row   : c, c+1
                float v2 = acc[mi][ni][2], v3 = acc[mi][ni][3];   // row+8 : c, c+1
                float h0,l0,h1,l1,h2,l2,h3,l3;
                if (r < 128) {
                    // q (r<64, scale 1/64) or k
                    __nv_bfloat16 *dh, *dl;
                    int d;
                    if (r < 64) {
                        d = r;
                        v0 *= (1.0f/HD_); v1 *= (1.0f/HD_);
                        v2 *= (1.0f/HD_); v3 *= (1.0f/HD_);
                        dh = g_aq_hi; dl = g_aq_lo;
                    } else {
                        d = r - 64;
                        dh = g_ak_hi; dl = g_ak_lo;
                    }
                    split1(v0,h0,l0); split1(v1,h1,l1);
                    split1(v2,h2,l2); split1(v3,h3,l3);
                    size_t i0 = ((size_t)bh * S_ + tokA) * HD_ + d;
                    size_t i1 = ((size_t)bh * S_ + tokB) * HD_ + d;
                    *(uint32_t*)(dh + i0) = pack_bf2(h0, h1);
                    *(uint32_t*)(dl + i0) = pack_bf2(l0, l1);
                    *(uint32_t*)(dh + i1) = pack_bf2(h2, h3);
                    *(uint32_t*)(dl + i1) = pack_bf2(l2, l3);
                } else {
                    // v -> transposed [bh][d][tok], 2B stores (16B runs across gid)
                    int d = r - 128;
                    split1(v0,h0,l0); split1(v1,h1,l1);
                    split1(v2,h2,l2); split1(v3,h3,l3);
                    size_t r0 = ((size_t)bh * HD_ + d)     * S_;
                    size_t r1 = ((size_t)bh * HD_ + d + 1) * S_;
                    g_avt_hi[r0 + tokA] = __float2bfloat16_rn(h0);
                    g_avt_hi[r1 + tokA] = __float2bfloat16_rn(h1);
                    g_avt_hi[r0 + tokB] = __float2bfloat16_rn(h2);
                    g_avt_hi[r1 + tokB] = __float2bfloat16_rn(h3);
                    g_avt_lo[r0 + tokA] = __float2bfloat16_rn(l0);
                    g_avt_lo[r1 + tokA] = __float2bfloat16_rn(l1);
                    g_avt_lo[r0 + tokB] = __float2bfloat16_rn(l2);
                    g_avt_lo[r1 + tokB] = __float2bfloat16_rn(l3);
                }
            }
        }
    }
}

// ---------------------------------------------------------------------------
// Tensor-core causal flash attention (unchanged, passing R7).
// ---------------------------------------------------------------------------
#define ROW_W   36
#define ARR_W   (64 * ROW_W)
#define BUF_W   (4 * ARR_W)
#define ATTN_SMEM_BYTES (2 * BUF_W * 4)

__global__ __launch_bounds__(256)
void attn_mma()
{
    extern __shared__ uint32_t smw[];
    const int tid  = threadIdx.x;
    const int w    = tid >> 5, lane = tid & 31;
    const int gid  = lane >> 2, tig = lane & 3;
    const int bx   = blockIdx.x, bh = blockIdx.y;
    const int b    = bh >> 4;
    const int h    = bh & 15;
    const int rA   = bx * 128 + w * 16 + gid;
    const int rB   = rA + 8;

    const uint32_t* qh_p = (const uint32_t*)(g_aq_hi + ((size_t)bh * S_ + bx*128 + w*16) * HD_);
    const uint32_t* ql_p = (const uint32_t*)(g_aq_lo + ((size_t)bh * S_ + bx*128 + w*16) * HD_);
    uint32_t qh[4][4], ql[4][4];
    #pragma unroll
    for (int kc = 0; kc < 4; kc++) {
        int w0 = 8*kc + tig;
        qh[kc][0] = qh_p[ gid      * 32 + w0    ];
        qh[kc][1] = qh_p[(gid + 8) * 32 + w0    ];
        qh[kc][2] = qh_p[ gid      * 32 + w0 + 4];
        qh[kc][3] = qh_p[(gid + 8) * 32 + w0 + 4];
        ql[kc][0] = ql_p[ gid      * 32 + w0    ];
        ql[kc][1] = ql_p[(gid + 8) * 32 + w0    ];
        ql[kc][2] = ql_p[ gid      * 32 + w0 + 4];
        ql[kc][3] = ql_p[(gid + 8) * 32 + w0 + 4];
    }

    float o[8][4] = {};
    float mA = -INFINITY, mB = -INFINITY, lA = 0.f, lB = 0.f;

    const __nv_bfloat16* kh_p = g_ak_hi  + (size_t)bh * S_ * HD_;
    const __nv_bfloat16* kl_p = g_ak_lo  + (size_t)bh * S_ * HD_;
    const __nv_bfloat16* vh_p = g_avt_hi + (size_t)bh * HD_ * S_;
    const __nv_bfloat16* vl_p = g_avt_lo + (size_t)bh * HD_ * S_;

    const uint32_t sb = (uint32_t)__cvta_generic_to_shared(smw);
    const int lr  = tid >> 3;
    const int seg = tid & 7;

    const uint32_t frag_off = (uint32_t)((lane & 7) * ROW_W * 4 + (lane >> 3) * 16);

    #define LOAD_KV(T, BUF) do {                                                \
        _Pragma("unroll")                                                       \
        for (int i = 0; i < 8; i++) {                                           \
            int arr = i >> 1;                                                   \
            int r   = (i & 1) * 32 + lr;                                        \
            uint32_t dst = sb + ((BUF)*BUF_W + arr*ARR_W + r*ROW_W + seg*4)*4;  \
            const __nv_bfloat16* srcp;                                          \
            if      (arr == 0) srcp = kh_p + (size_t)((T)*64 + r) * HD_ + seg*8;\
            else if (arr == 1) srcp = kl_p + (size_t)((T)*64 + r) * HD_ + seg*8;\
            else if (arr == 2) srcp = vh_p + (size_t)r * S_ + (T)*64 + seg*8;   \
            else               srcp = vl_p + (size_t)r * S_ + (T)*64 + seg*8;   \
            asm volatile("cp.async.cg.shared.global [%0], [%1], 16;\n"          \
                :: "r"(dst), "l"(srcp));                                        \
        }                                                                       \
        asm volatile("cp.async.commit_group;\n");                               \
    } while (0)

    const int nt = 2 * (bx + 1);
    LOAD_KV(0, 0);

    for (int t = 0; t < nt; t++) {
        const int buf = t & 1;
        if (t + 1 < nt) {
            LOAD_KV(t + 1, (t + 1) & 1);
            asm volatile("cp.async.wait_group 1;\n");
        } else {
            asm volatile("cp.async.wait_group 0;\n");
        }
        __syncthreads();

        const uint32_t sKH = sb + (uint32_t)(buf * BUF_W) * 4;
        const uint32_t sKL = sKH + ARR_W * 4;
        const uint32_t sVH = sKH + 2 * ARR_W * 4;
        const uint32_t sVL = sKH + 3 * ARR_W * 4;

        float s[8][4];
        #pragma unroll
        for (int ni = 0; ni < 8; ni++) { s[ni][0]=0; s[ni][1]=0; s[ni][2]=0; s[ni][3]=0; }
        #pragma unroll
        for (int ni = 0; ni < 8; ni++) {
            uint32_t off = (uint32_t)(ni * 8 * ROW_W * 4) + frag_off;
            #pragma unroll
            for (int kp = 0; kp < 2; kp++) {
                uint32_t bh4[4], bl4[4];
                ldsm_x4(bh4, sKH + off + kp*64);
                ldsm_x4(bl4, sKL + off + kp*64);
                mma16816(s[ni], qh[2*kp],   bh4);
                mma16816(s[ni], qh[2*kp],   bl4);
                mma16816(s[ni], ql[2*kp],   bh4);
                mma16816(s[ni], qh[2*kp+1], bh4 + 2);
                mma16816(s[ni], qh[2*kp+1], bl4 + 2);
                mma16816(s[ni], ql[2*kp+1], bh4 + 2);
            }
        }

        if (t >= 2 * bx) {
            #pragma unroll
            for (int ni = 0; ni < 8; ni++) {
                int c0 = t * 64 + ni * 8 + 2 * tig;
                if (c0     > rA) s[ni][0] = -1e30f;
                if (c0 + 1 > rA) s[ni][1] = -1e30f;
                if (c0     > rB) s[ni][2] = -1e30f;
                if (c0 + 1 > rB) s[ni][3] = -1e30f;
            }
        }

        float tmA = -INFINITY, tmB = -INFINITY;
        #pragma unroll
        for (int ni = 0; ni < 8; ni++) {
            tmA = fmaxf(tmA, fmaxf(s[ni][0], s[ni][1]));
            tmB = fmaxf(tmB, fmaxf(s[ni][2], s[ni][3]));
        }
        tmA = fmaxf(tmA, __shfl_xor_sync(0xffffffffu, tmA, 1));
        tmA = fmaxf(tmA, __shfl_xor_sync(0xffffffffu, tmA, 2));
        tmB = fmaxf(tmB, __shfl_xor_sync(0xffffffffu, tmB, 1));
        tmB = fmaxf(tmB, __shfl_xor_sync(0xffffffffu, tmB, 2));

        float mnA = fmaxf(mA, tmA), mnB = fmaxf(mB, tmB);
        float sfA = __expf(mA - mnA), sfB = __expf(mB - mnB);
        float lsA = 0.f, lsB = 0.f;

        uint32_t ph[4][4], pl[4][4];
        #pragma unroll
        for (int ni = 0; ni < 8; ni++) {
            float e0 = __expf(s[ni][0] - mnA);
            float e1 = __expf(s[ni][1] - mnA);
            float e2 = __expf(s[ni][2] - mnB);
            float e3 = __expf(s[ni][3] - mnB);
            lsA += e0 + e1;  lsB += e2 + e3;
            float h0,l0,h1,l1,h2,l2,h3,l3;
            split1(e0,h0,l0); split1(e1,h1,l1); split1(e2,h2,l2); split1(e3,h3,l3);
            int kc = ni >> 1, off = (ni & 1) * 2;
            ph[kc][off]     = pack_bf2(h0, h1);
            ph[kc][off + 1] = pack_bf2(h2, h3);
            pl[kc][off]     = pack_bf2(l0, l1);
            pl[kc][off + 1] = pack_bf2(l2, l3);
        }
        lsA += __shfl_xor_sync(0xffffffffu, lsA, 1);
        lsA += __shfl_xor_sync(0xffffffffu, lsA, 2);
        lsB += __shfl_xor_sync(0xffffffffu, lsB, 1);
        lsB += __shfl_xor_sync(0xffffffffu, lsB, 2);

        mA = mnA; mB = mnB;
        lA = lA * sfA + lsA;
        lB = lB * sfB + lsB;

        #pragma unroll
        for (int nd = 0; nd < 8; nd++) {
            o[nd][0] *= sfA; o[nd][1] *= sfA;
            o[nd][2] *= sfB; o[nd][3] *= sfB;
        }

        #pragma unroll
        for (int nd = 0; nd < 8; nd++) {
            uint32_t off = (uint32_t)(nd * 8 * ROW_W * 4) + frag_off;
            #pragma unroll
            for (int kp = 0; kp < 2; kp++) {
                uint32_t vh4[4], vl4[4];
                ldsm_x4(vh4, sVH + off + kp*64);
                ldsm_x4(vl4, sVL + off + kp*64);
                mma16816(o[nd], ph[2*kp],   vh4);
                mma16816(o[nd], ph[2*kp],   vl4);
                mma16816(o[nd], pl[2*kp],   vh4);
                mma16816(o[nd], ph[2*kp+1], vh4 + 2);
                mma16816(o[nd], ph[2*kp+1], vl4 + 2);
                mma16816(o[nd], pl[2*kp+1], vh4 + 2);
            }
        }
        __syncthreads();
    }
    #undef LOAD_KV

    const float iA = 1.0f / lA, iB = 1.0f / lB;
    const size_t gRowA = (size_t)(b * S_ + rA);
    const size_t gRowB = (size_t)(b * S_ + rB);
    #pragma unroll
    for (int nd = 0; nd < 8; nd++) {
        float v0 = o[nd][0] * iA, v1 = o[nd][1] * iA;
        float v2 = o[nd][2] * iB, v3 = o[nd][3] * iB;
        float h0,l0,h1,l1,h2,l2,h3,l3;
        split1(v0,h0,l0); split1(v1,h1,l1); split1(v2,h2,l2); split1(v3,h3,l3);
        size_t i0 = gRowA * D_ + h * HD_ + nd * 8 + 2 * tig;
        size_t i1 = gRowB * D_ + h * HD_ + nd * 8 + 2 * tig;
        *(uint32_t*)(g_at_hi + i0) = pack_bf2(h0, h1);
        *(uint32_t*)(g_at_lo + i0) = pack_bf2(l0, l1);
        *(uint32_t*)(g_at_hi + i1) = pack_bf2(h2, h3);
        *(uint32_t*)(g_at_lo + i1) = pack_bf2(l2, l3);
    }
}

// ---------------------------------------------------------------------------
extern "C" void kernel_launch(void* const* d_in, const int* in_sizes, int n_in,
                              void* d_out, int out_size)
{
    const float* x = nullptr, *w_qkv = nullptr, *w_out = nullptr, *b_out = nullptr;
    for (int i = 0; i < n_in; i++) {
        long long n = in_sizes[i];
        if      (n == (long long)B_ * S_ * D_)      x     = (const float*)d_in[i];
        else if (n == (long long)N_QKV * D_)        w_qkv = (const float*)d_in[i];
        else if (n == (long long)D_ * D_)           w_out = (const float*)d_in[i];
        else if (n == (long long)D_)                b_out = (const float*)d_in[i];
        // mask ignored: causality is static
    }
    float* out = (float*)d_out;

    cudaFuncSetAttribute(attn_mma, cudaFuncAttributeMaxDynamicSharedMemorySize,
                         ATTN_SMEM_BYTES);
    cudaFuncSetAttribute(gemm_bf16x3<0>, cudaFuncAttributeMaxDynamicSharedMemorySize,
                         GEMM_SMEM_BYTES);
    cudaFuncSetAttribute(gemm_bf16x3<1>, cudaFuncAttributeMaxDynamicSharedMemorySize,
                         GEMM_SMEM_BYTES);

    // 0) Split GEMM inputs into bf16 hi/lo
    split_bf16<0><<<4096, 256>>>(x,     (M_TOT * D_) / 4);
    split_bf16<1><<<3072, 256>>>(w_qkv, (N_QKV * D_) / 4);
    split_bf16<2><<<1024, 256>>>(w_out, (D_ * D_) / 4);

    // 1) QKV projection + fused repack (epilogue writes q/64, K, V^T splits)
    gemm_bf16x3<0><<<dim3(N_QKV / 128, M_TOT / 128), 256, GEMM_SMEM_BYTES>>>(
        nullptr, nullptr, M_TOT, N_QKV, D_);

    // 2) Tensor-core causal flash attention -> g_at_hi/lo
    attn_mma<<<dim3(S_ / 128, B_ * H_), 256, ATTN_SMEM_BYTES>>>();

    // 3) Output projection: out = attn @ w_out^T + b_out
    gemm_bf16x3<1><<<dim3(D_ / 128, M_TOT / 128), 256, GEMM_SMEM_BYTES>>>(
        b_out, out, M_TOT, D_, D_);
}

// round 10
// speedup vs baseline: 3.0041x; 1.0104x over previous
#include <cuda_runtime.h>
#include <cuda_bf16.h>
#include <stdint.h>
#include <math.h>

// Problem constants
#define B_   2
#define S_   2048
#define D_   1024
#define H_   16
#define HD_  64
#define M_TOT (B_*S_)     // 4096
#define N_QKV (3*D_)      // 3072

// ---------------------------------------------------------------------------
// Scratch (allocation-free rule: __device__ globals)
// ---------------------------------------------------------------------------
__device__ __nv_bfloat16 g_x_hi [(size_t)M_TOT * D_];
__device__ __nv_bfloat16 g_x_lo [(size_t)M_TOT * D_];
__device__ __nv_bfloat16 g_wq_hi[(size_t)N_QKV * D_];
__device__ __nv_bfloat16 g_wq_lo[(size_t)N_QKV * D_];
__device__ __nv_bfloat16 g_at_hi[(size_t)M_TOT * D_];   // attention out (split)
__device__ __nv_bfloat16 g_at_lo[(size_t)M_TOT * D_];
__device__ __nv_bfloat16 g_wo_hi[(size_t)D_ * D_];
__device__ __nv_bfloat16 g_wo_lo[(size_t)D_ * D_];

// Head-contiguous attention operands (split), written by gemm0 epilogue
__device__ __nv_bfloat16 g_aq_hi [(size_t)B_*H_*S_*HD_];  // [bh][S][64], q/64
__device__ __nv_bfloat16 g_aq_lo [(size_t)B_*H_*S_*HD_];
__device__ __nv_bfloat16 g_ak_hi [(size_t)B_*H_*S_*HD_];  // [bh][S][64]
__device__ __nv_bfloat16 g_ak_lo [(size_t)B_*H_*S_*HD_];
__device__ __nv_bfloat16 g_avt_hi[(size_t)B_*H_*HD_*S_];  // [bh][64][S]  (V^T)
__device__ __nv_bfloat16 g_avt_lo[(size_t)B_*H_*HD_*S_];

// ---------------------------------------------------------------------------
// helpers
// ---------------------------------------------------------------------------
__device__ __forceinline__ uint32_t pack_bf2(float lo, float hi) {
    __nv_bfloat162 t = __floats2bfloat162_rn(lo, hi);   // .x = lo half
    return *(uint32_t*)&t;
}
__device__ __forceinline__ void split1(float v, float& h, float& l) {
    __nv_bfloat16 hb = __float2bfloat16_rn(v);
    h = __bfloat162float(hb);
    l = v - h;
}
__device__ __forceinline__ void mma16816(float* c, const uint32_t* a, const uint32_t* b)
{
    asm volatile(
        "mma.sync.aligned.m16n8k16.row.col.f32.bf16.bf16.f32 "
        "{%0,%1,%2,%3}, {%4,%5,%6,%7}, {%8,%9}, {%0,%1,%2,%3};\n"
        : "+f"(c[0]), "+f"(c[1]), "+f"(c[2]), "+f"(c[3])
        : "r"(a[0]), "r"(a[1]), "r"(a[2]), "r"(a[3]), "r"(b[0]), "r"(b[1]));
}
__device__ __forceinline__ void ldsm_x4(uint32_t* r, uint32_t addr)
{
    asm volatile(
        "ldmatrix.sync.aligned.m8n8.x4.shared.b16 {%0,%1,%2,%3}, [%4];\n"
        : "=r"(r[0]), "=r"(r[1]), "=r"(r[2]), "=r"(r[3]) : "r"(addr));
}

// ---------------------------------------------------------------------------
// Elementwise split for GEMM inputs: a -> (hi, lo)
// ---------------------------------------------------------------------------
template<int ID>
__global__ void split_bf16(const float* __restrict__ src, int n4)
{
    __nv_bfloat16* hi = (ID == 0) ? g_x_hi : (ID == 1) ? g_wq_hi : g_wo_hi;
    __nv_bfloat16* lo = (ID == 0) ? g_x_lo : (ID == 1) ? g_wq_lo : g_wo_lo;

    for (int i = blockIdx.x * blockDim.x + threadIdx.x; i < n4;
         i += gridDim.x * blockDim.x) {
        float4 v = ((const float4*)src)[i];
        float h0,l0,h1,l1,h2,l2,h3,l3;
        split1(v.x,h0,l0); split1(v.y,h1,l1); split1(v.z,h2,l2); split1(v.w,h3,l3);
        ((uint32_t*)hi)[2*i + 0] = pack_bf2(h0, h1);
        ((uint32_t*)hi)[2*i + 1] = pack_bf2(h2, h3);
        ((uint32_t*)lo)[2*i + 0] = pack_bf2(l0, l1);
        ((uint32_t*)lo)[2*i + 1] = pack_bf2(l2, l3);
    }
}

// ---------------------------------------------------------------------------
// bf16x3-split tensor-core NT GEMM.
// Mainloop mma order is TERM-MAJOR inside each np: same-accumulator distance
// is 4 mma (~32 cyc) >= HMMA latency, so the 3-term chain no longer stalls.
// MODE 0: epilogue fuses the qkv repack. MODE 1: C = d_out + bias.
// ---------------------------------------------------------------------------
#define GLDW 20
#define GARR (128 * GLDW)
#define GSTG (4 * GARR)
#define GEMM_SMEM_BYTES (2 * GSTG * 4)   // 81920

template<int MODE>
__global__ __launch_bounds__(256, 2)
void gemm_bf16x3(const float* __restrict__ bias, float* __restrict__ C_out,
                 int M, int N, int K)
{
    extern __shared__ uint32_t gsm[];

    const __nv_bfloat16 *Ah, *Al, *Bh, *Bl;
    if (MODE == 0) { Ah = g_x_hi;  Al = g_x_lo;  Bh = g_wq_hi; Bl = g_wq_lo; }
    else           { Ah = g_at_hi; Al = g_at_lo; Bh = g_wo_hi; Bl = g_wo_lo; }

    const int tid  = threadIdx.x;
    const int lane = tid & 31;
    const int warp = tid >> 5;
    const int wr = warp >> 1, wc = warp & 1;
    const int gid = lane >> 2, tig = lane & 3;

    const int bm = blockIdx.y * 128;
    const int bn = blockIdx.x * 128;

    const int lrow   = tid >> 2;
    const int lchunk = tid & 3;

    const uint32_t sb = (uint32_t)__cvta_generic_to_shared(gsm);

    #define G_LOAD(T, S) do {                                                   \
        int k0_ = (T) * 32;                                                     \
        _Pragma("unroll")                                                       \
        for (int hh = 0; hh < 2; hh++) {                                        \
            int row = lrow + hh * 64;                                           \
            uint32_t d0 = sb + (uint32_t)((S)*GSTG + row*GLDW + lchunk*4) * 4;  \
            size_t asrc = (size_t)(bm + row) * K + k0_ + lchunk*8;              \
            size_t bsrc = (size_t)(bn + row) * K + k0_ + lchunk*8;              \
            asm volatile("cp.async.cg.shared.global [%0], [%1], 16;\n"          \
                :: "r"(d0),              "l"(Ah + asrc));                       \
            asm volatile("cp.async.cg.shared.global [%0], [%1], 16;\n"          \
                :: "r"(d0 + GARR*4),     "l"(Al + asrc));                       \
            asm volatile("cp.async.cg.shared.global [%0], [%1], 16;\n"          \
                :: "r"(d0 + 2*GARR*4),   "l"(Bh + bsrc));                       \
            asm volatile("cp.async.cg.shared.global [%0], [%1], 16;\n"          \
                :: "r"(d0 + 3*GARR*4),   "l"(Bl + bsrc));                       \
        }                                                                       \
        asm volatile("cp.async.commit_group;\n");                               \
    } while (0)

    uint32_t a_off[2], b_off[4];
    #pragma unroll
    for (int mi = 0; mi < 2; mi++)
        a_off[mi] = (uint32_t)((wr*32 + mi*16 + (lane & 15)) * GLDW * 4
                               + (lane >> 4) * 16);
    #pragma unroll
    for (int np = 0; np < 4; np++)
        b_off[np] = (uint32_t)((wc*64 + np*16 + ((lane >> 4) & 1)*8 + (lane & 7))
                               * GLDW * 4 + ((lane >> 3) & 1) * 16);

    float acc[2][8][4] = {};

    const int nt = K / 32;
    G_LOAD(0, 0);

    for (int t = 0; t < nt; t++) {
        const int stg = t & 1;
        if (t + 1 < nt) {
            G_LOAD(t + 1, (t + 1) & 1);
            asm volatile("cp.async.wait_group 1;\n");
        } else {
            asm volatile("cp.async.wait_group 0;\n");
        }
        __syncthreads();

        const uint32_t sAh = sb + (uint32_t)(stg * GSTG) * 4;
        const uint32_t sAl = sAh + GARR * 4;
        const uint32_t sBh = sAh + 2 * GARR * 4;
        const uint32_t sBl = sAh + 3 * GARR * 4;

        #pragma unroll
        for (int kcb = 0; kcb < 2; kcb++) {
            uint32_t ah[2][4], al[2][4];
            ldsm_x4(ah[0], sAh + a_off[0] + kcb*32);
            ldsm_x4(ah[1], sAh + a_off[1] + kcb*32);
            ldsm_x4(al[0], sAl + a_off[0] + kcb*32);
            ldsm_x4(al[1], sAl + a_off[1] + kcb*32);
            #pragma unroll
            for (int np = 0; np < 4; np++) {
                uint32_t bhf[4], blf[4];
                ldsm_x4(bhf, sBh + b_off[np] + kcb*32);
                ldsm_x4(blf, sBl + b_off[np] + kcb*32);
                // term-major: same-acc distance = 4 mma
                #pragma unroll
                for (int term = 0; term < 3; term++) {
                    #pragma unroll
                    for (int sub = 0; sub < 2; sub++) {
                        #pragma unroll
                        for (int mi = 0; mi < 2; mi++) {
                            int ni = np * 2 + sub;
                            if      (term == 0) mma16816(acc[mi][ni], ah[mi], bhf + sub*2);
                            else if (term == 1) mma16816(acc[mi][ni], ah[mi], blf + sub*2);
                            else                mma16816(acc[mi][ni], al[mi], bhf + sub*2);
                        }
                    }
                }
            }
        }
        __syncthreads();
    }
    #undef G_LOAD

    // ---- Epilogue ----
    if (MODE == 1) {
        #pragma unroll
        for (int mi = 0; mi < 2; mi++) {
            int row = bm + wr * 32 + mi * 16 + gid;
            #pragma unroll
            for (int ni = 0; ni < 8; ni++) {
                int col = bn + wc * 64 + ni * 8 + tig * 2;
                float2 bv = *(const float2*)(bias + col);
                float2 v0 = make_float2(acc[mi][ni][0] + bv.x, acc[mi][ni][1] + bv.y);
                float2 v1 = make_float2(acc[mi][ni][2] + bv.x, acc[mi][ni][3] + bv.y);
                *(float2*)(C_out + (size_t)row * N + col)       = v0;
                *(float2*)(C_out + (size_t)(row + 8) * N + col) = v1;
            }
        }
    } else {
        // Fused qkv repack
        #pragma unroll
        for (int mi = 0; mi < 2; mi++) {
            const int row  = bm + wr * 32 + mi * 16 + gid;
            const int bidx = row >> 11;
            const int tokA = row & 2047;
            const int tokB = tokA + 8;
            #pragma unroll
            for (int ni = 0; ni < 8; ni++) {
                int col = bn + wc * 64 + ni * 8 + tig * 2;
                int h   = col / 192;
                int r   = col - h * 192;
                int bh  = bidx * H_ + h;
                float v0 = acc[mi][ni][0], v1 = acc[mi][ni][1];
                float v2 = acc[mi][ni][2], v3 = acc[mi][ni][3];
                float h0,l0,h1,l1,h2,l2,h3,l3;
                if (r < 128) {
                    __nv_bfloat16 *dh, *dl;
                    int d;
                    if (r < 64) {
                        d = r;
                        v0 *= (1.0f/HD_); v1 *= (1.0f/HD_);
                        v2 *= (1.0f/HD_); v3 *= (1.0f/HD_);
                        dh = g_aq_hi; dl = g_aq_lo;
                    } else {
                        d = r - 64;
                        dh = g_ak_hi; dl = g_ak_lo;
                    }
                    split1(v0,h0,l0); split1(v1,h1,l1);
                    split1(v2,h2,l2); split1(v3,h3,l3);
                    size_t i0 = ((size_t)bh * S_ + tokA) * HD_ + d;
                    size_t i1 = ((size_t)bh * S_ + tokB) * HD_ + d;
                    *(uint32_t*)(dh + i0) = pack_bf2(h0, h1);
                    *(uint32_t*)(dl + i0) = pack_bf2(l0, l1);
                    *(uint32_t*)(dh + i1) = pack_bf2(h2, h3);
                    *(uint32_t*)(dl + i1) = pack_bf2(l2, l3);
                } else {
                    int d = r - 128;
                    split1(v0,h0,l0); split1(v1,h1,l1);
                    split1(v2,h2,l2); split1(v3,h3,l3);
                    size_t r0 = ((size_t)bh * HD_ + d)     * S_;
                    size_t r1 = ((size_t)bh * HD_ + d + 1) * S_;
                    g_avt_hi[r0 + tokA] = __float2bfloat16_rn(h0);
                    g_avt_hi[r1 + tokA] = __float2bfloat16_rn(h1);
                    g_avt_hi[r0 + tokB] = __float2bfloat16_rn(h2);
                    g_avt_hi[r1 + tokB] = __float2bfloat16_rn(h3);
                    g_avt_lo[r0 + tokA] = __float2bfloat16_rn(l0);
                    g_avt_lo[r1 + tokA] = __float2bfloat16_rn(l1);
                    g_avt_lo[r0 + tokB] = __float2bfloat16_rn(l2);
                    g_avt_lo[r1 + tokB] = __float2bfloat16_rn(l3);
                }
            }
        }
    }
}

// ---------------------------------------------------------------------------
// Tensor-core causal flash attention.
// QK and PV mainloops process ni in PAIRS with interleaved mma chains:
// same-accumulator distance 2 instead of 6 back-to-back.
// ---------------------------------------------------------------------------
#define ROW_W   36
#define ARR_W   (64 * ROW_W)
#define BUF_W   (4 * ARR_W)
#define ATTN_SMEM_BYTES (2 * BUF_W * 4)

__global__ __launch_bounds__(256)
void attn_mma()
{
    extern __shared__ uint32_t smw[];
    const int tid  = threadIdx.x;
    const int w    = tid >> 5, lane = tid & 31;
    const int gid  = lane >> 2, tig = lane & 3;
    const int bx   = blockIdx.x, bh = blockIdx.y;
    const int b    = bh >> 4;
    const int h    = bh & 15;
    const int rA   = bx * 128 + w * 16 + gid;
    const int rB   = rA + 8;

    const uint32_t* qh_p = (const uint32_t*)(g_aq_hi + ((size_t)bh * S_ + bx*128 + w*16) * HD_);
    const uint32_t* ql_p = (const uint32_t*)(g_aq_lo + ((size_t)bh * S_ + bx*128 + w*16) * HD_);
    uint32_t qh[4][4], ql[4][4];
    #pragma unroll
    for (int kc = 0; kc < 4; kc++) {
        int w0 = 8*kc + tig;
        qh[kc][0] = qh_p[ gid      * 32 + w0    ];
        qh[kc][1] = qh_p[(gid + 8) * 32 + w0    ];
        qh[kc][2] = qh_p[ gid      * 32 + w0 + 4];
        qh[kc][3] = qh_p[(gid + 8) * 32 + w0 + 4];
        ql[kc][0] = ql_p[ gid      * 32 + w0    ];
        ql[kc][1] = ql_p[(gid + 8) * 32 + w0    ];
        ql[kc][2] = ql_p[ gid      * 32 + w0 + 4];
        ql[kc][3] = ql_p[(gid + 8) * 32 + w0 + 4];
    }

    float o[8][4] = {};
    float mA = -INFINITY, mB = -INFINITY, lA = 0.f, lB = 0.f;

    const __nv_bfloat16* kh_p = g_ak_hi  + (size_t)bh * S_ * HD_;
    const __nv_bfloat16* kl_p = g_ak_lo  + (size_t)bh * S_ * HD_;
    const __nv_bfloat16* vh_p = g_avt_hi + (size_t)bh * HD_ * S_;
    const __nv_bfloat16* vl_p = g_avt_lo + (size_t)bh * HD_ * S_;

    const uint32_t sb = (uint32_t)__cvta_generic_to_shared(smw);
    const int lr  = tid >> 3;
    const int seg = tid & 7;

    const uint32_t frag_off = (uint32_t)((lane & 7) * ROW_W * 4 + (lane >> 3) * 16);

    #define LOAD_KV(T, BUF) do {                                                \
        _Pragma("unroll")                                                       \
        for (int i = 0; i < 8; i++) {                                           \
            int arr = i >> 1;                                                   \
            int r   = (i & 1) * 32 + lr;                                        \
            uint32_t dst = sb + ((BUF)*BUF_W + arr*ARR_W + r*ROW_W + seg*4)*4;  \
            const __nv_bfloat16* srcp;                                          \
            if      (arr == 0) srcp = kh_p + (size_t)((T)*64 + r) * HD_ + seg*8;\
            else if (arr == 1) srcp = kl_p + (size_t)((T)*64 + r) * HD_ + seg*8;\
            else if (arr == 2) srcp = vh_p + (size_t)r * S_ + (T)*64 + seg*8;   \
            else               srcp = vl_p + (size_t)r * S_ + (T)*64 + seg*8;   \
            asm volatile("cp.async.cg.shared.global [%0], [%1], 16;\n"          \
                :: "r"(dst), "l"(srcp));                                        \
        }                                                                       \
        asm volatile("cp.async.commit_group;\n");                               \
    } while (0)

    // 12 interleaved mma for an (acc0, acc1) pair given hi/lo B-fragments of
    // one kp (kc = 2kp, 2kp+1). AH/AL are the hi/lo A-fragment arrays (q or p).
    #define MMA_PAIR(ACC0, ACC1, AH, AL, F0H, F0L, F1H, F1L, KP) do {           \
        mma16816(ACC0, AH[2*(KP)],   F0H);     mma16816(ACC1, AH[2*(KP)],   F1H);     \
        mma16816(ACC0, AH[2*(KP)],   F0L);     mma16816(ACC1, AH[2*(KP)],   F1L);     \
        mma16816(ACC0, AL[2*(KP)],   F0H);     mma16816(ACC1, AL[2*(KP)],   F1H);     \
        mma16816(ACC0, AH[2*(KP)+1], F0H + 2); mma16816(ACC1, AH[2*(KP)+1], F1H + 2); \
        mma16816(ACC0, AH[2*(KP)+1], F0L + 2); mma16816(ACC1, AH[2*(KP)+1], F1L + 2); \
        mma16816(ACC0, AL[2*(KP)+1], F0H + 2); mma16816(ACC1, AL[2*(KP)+1], F1H + 2); \
    } while (0)

    const int nt = 2 * (bx + 1);
    LOAD_KV(0, 0);

    for (int t = 0; t < nt; t++) {
        const int buf = t & 1;
        if (t + 1 < nt) {
            LOAD_KV(t + 1, (t + 1) & 1);
            asm volatile("cp.async.wait_group 1;\n");
        } else {
            asm volatile("cp.async.wait_group 0;\n");
        }
        __syncthreads();

        const uint32_t sKH = sb + (uint32_t)(buf * BUF_W) * 4;
        const uint32_t sKL = sKH + ARR_W * 4;
        const uint32_t sVH = sKH + 2 * ARR_W * 4;
        const uint32_t sVL = sKH + 3 * ARR_W * 4;

        // ---- S = Q @ K^T (ni pairs, interleaved chains) ----
        float s[8][4];
        #pragma unroll
        for (int ni = 0; ni < 8; ni++) { s[ni][0]=0; s[ni][1]=0; s[ni][2]=0; s[ni][3]=0; }
        #pragma unroll
        for (int nn = 0; nn < 4; nn++) {
            uint32_t off0 = (uint32_t)((2*nn)   * 8 * ROW_W * 4) + frag_off;
            uint32_t off1 = (uint32_t)((2*nn+1) * 8 * ROW_W * 4) + frag_off;
            #pragma unroll
            for (int kp = 0; kp < 2; kp++) {
                uint32_t k0h[4], k0l[4], k1h[4], k1l[4];
                ldsm_x4(k0h, sKH + off0 + kp*64);
                ldsm_x4(k0l, sKL + off0 + kp*64);
                ldsm_x4(k1h, sKH + off1 + kp*64);
                ldsm_x4(k1l, sKL + off1 + kp*64);
                MMA_PAIR(s[2*nn], s[2*nn+1], qh, ql, k0h, k0l, k1h, k1l, kp);
            }
        }

        // ---- causal mask (only diagonal tiles) ----
        if (t >= 2 * bx) {
            #pragma unroll
            for (int ni = 0; ni < 8; ni++) {
                int c0 = t * 64 + ni * 8 + 2 * tig;
                if (c0     > rA) s[ni][0] = -1e30f;
                if (c0 + 1 > rA) s[ni][1] = -1e30f;
                if (c0     > rB) s[ni][2] = -1e30f;
                if (c0 + 1 > rB) s[ni][3] = -1e30f;
            }
        }

        // ---- online softmax ----
        float tmA = -INFINITY, tmB = -INFINITY;
        #pragma unroll
        for (int ni = 0; ni < 8; ni++) {
            tmA = fmaxf(tmA, fmaxf(s[ni][0], s[ni][1]));
            tmB = fmaxf(tmB, fmaxf(s[ni][2], s[ni][3]));
        }
        tmA = fmaxf(tmA, __shfl_xor_sync(0xffffffffu, tmA, 1));
        tmA = fmaxf(tmA, __shfl_xor_sync(0xffffffffu, tmA, 2));
        tmB = fmaxf(tmB, __shfl_xor_sync(0xffffffffu, tmB, 1));
        tmB = fmaxf(tmB, __shfl_xor_sync(0xffffffffu, tmB, 2));

        float mnA = fmaxf(mA, tmA), mnB = fmaxf(mB, tmB);
        float sfA = __expf(mA - mnA), sfB = __expf(mB - mnB);
        float lsA = 0.f, lsB = 0.f;

        uint32_t ph[4][4], pl[4][4];
        #pragma unroll
        for (int ni = 0; ni < 8; ni++) {
            float e0 = __expf(s[ni][0] - mnA);
            float e1 = __expf(s[ni][1] - mnA);
            float e2 = __expf(s[ni][2] - mnB);
            float e3 = __expf(s[ni][3] - mnB);
            lsA += e0 + e1;  lsB += e2 + e3;
            float h0,l0,h1,l1,h2,l2,h3,l3;
            split1(e0,h0,l0); split1(e1,h1,l1); split1(e2,h2,l2); split1(e3,h3,l3);
            int kc = ni >> 1, off = (ni & 1) * 2;
            ph[kc][off]     = pack_bf2(h0, h1);
            ph[kc][off + 1] = pack_bf2(h2, h3);
            pl[kc][off]     = pack_bf2(l0, l1);
            pl[kc][off + 1] = pack_bf2(l2, l3);
        }
        lsA += __shfl_xor_sync(0xffffffffu, lsA, 1);
        lsA += __shfl_xor_sync(0xffffffffu, lsA, 2);
        lsB += __shfl_xor_sync(0xffffffffu, lsB, 1);
        lsB += __shfl_xor_sync(0xffffffffu, lsB, 2);

        mA = mnA; mB = mnB;
        lA = lA * sfA + lsA;
        lB = lB * sfB + lsB;

        #pragma unroll
        for (int nd = 0; nd < 8; nd++) {
            o[nd][0] *= sfA; o[nd][1] *= sfA;
            o[nd][2] *= sfB; o[nd][3] *= sfB;
        }

        // ---- O += P @ V (nd pairs, interleaved chains) ----
        #pragma unroll
        for (int nn = 0; nn < 4; nn++) {
            uint32_t off0 = (uint32_t)((2*nn)   * 8 * ROW_W * 4) + frag_off;
            uint32_t off1 = (uint32_t)((2*nn+1) * 8 * ROW_W * 4) + frag_off;
            #pragma unroll
            for (int kp = 0; kp < 2; kp++) {
                uint32_t v0h[4], v0l[4], v1h[4], v1l[4];
                ldsm_x4(v0h, sVH + off0 + kp*64);
                ldsm_x4(v0l, sVL + off0 + kp*64);
                ldsm_x4(v1h, sVH + off1 + kp*64);
                ldsm_x4(v1l, sVL + off1 + kp*64);
                MMA_PAIR(o[2*nn], o[2*nn+1], ph, pl, v0h, v0l, v1h, v1l, kp);
            }
        }
        __syncthreads();
    }
    #undef LOAD_KV
    #undef MMA_PAIR

    const float iA = 1.0f / lA, iB = 1.0f / lB;
    const size_t gRowA = (size_t)(b * S_ + rA);
    const size_t gRowB = (size_t)(b * S_ + rB);
    #pragma unroll
    for (int nd = 0; nd < 8; nd++) {
        float v0 = o[nd][0] * iA, v1 = o[nd][1] * iA;
        float v2 = o[nd][2] * iB, v3 = o[nd][3] * iB;
        float h0,l0,h1,l1,h2,l2,h3,l3;
        split1(v0,h0,l0); split1(v1,h1,l1); split1(v2,h2,l2); split1(v3,h3,l3);
        size_t i0 = gRowA * D_ + h * HD_ + nd * 8 + 2 * tig;
        size_t i1 = gRowB * D_ + h * HD_ + nd * 8 + 2 * tig;
        *(uint32_t*)(g_at_hi + i0) = pack_bf2(h0, h1);
        *(uint32_t*)(g_at_lo + i0) = pack_bf2(l0, l1);
        *(uint32_t*)(g_at_hi + i1) = pack_bf2(h2, h3);
        *(uint32_t*)(g_at_lo + i1) = pack_bf2(l2, l3);
    }
}

// ---------------------------------------------------------------------------
extern "C" void kernel_launch(void* const* d_in, const int* in_sizes, int n_in,
                              void* d_out, int out_size)
{
    const float* x = nullptr, *w_qkv = nullptr, *w_out = nullptr, *b_out = nullptr;
    for (int i = 0; i < n_in; i++) {
        long long n = in_sizes[i];
        if      (n == (long long)B_ * S_ * D_)      x     = (const float*)d_in[i];
        else if (n == (long long)N_QKV * D_)        w_qkv = (const float*)d_in[i];
        else if (n == (long long)D_ * D_)           w_out = (const float*)d_in[i];
        else if (n == (long long)D_)                b_out = (const float*)d_in[i];
        // mask ignored: causality is static
    }
    float* out = (float*)d_out;

    cudaFuncSetAttribute(attn_mma, cudaFuncAttributeMaxDynamicSharedMemorySize,
                         ATTN_SMEM_BYTES);
    cudaFuncSetAttribute(gemm_bf16x3<0>, cudaFuncAttributeMaxDynamicSharedMemorySize,
                         GEMM_SMEM_BYTES);
    cudaFuncSetAttribute(gemm_bf16x3<1>, cudaFuncAttributeMaxDynamicSharedMemorySize,
                         GEMM_SMEM_BYTES);

    // 0) Split GEMM inputs into bf16 hi/lo
    split_bf16<0><<<4096, 256>>>(x,     (M_TOT * D_) / 4);
    split_bf16<1><<<3072, 256>>>(w_qkv, (N_QKV * D_) / 4);
    split_bf16<2><<<1024, 256>>>(w_out, (D_ * D_) / 4);

    // 1) QKV projection + fused repack
    gemm_bf16x3<0><<<dim3(N_QKV / 128, M_TOT / 128), 256, GEMM_SMEM_BYTES>>>(
        nullptr, nullptr, M_TOT, N_QKV, D_);

    // 2) Tensor-core causal flash attention -> g_at_hi/lo
    attn_mma<<<dim3(S_ / 128, B_ * H_), 256, ATTN_SMEM_BYTES>>>();

    // 3) Output projection: out = attn @ w_out^T + b_out
    gemm_bf16x3<1><<<dim3(D_ / 128, M_TOT / 128), 256, GEMM_SMEM_BYTES>>>(
        b_out, out, M_TOT, D_, D_);
}